// round 2
// baseline (speedup 1.0000x reference)
#include <cuda_runtime.h>
#include <math.h>

#define S_LEN 120
#define T_LEN 10
#define B_SZ  128
#define E_DIM 80
#define HW    75
#define HS    700
#define NW    (S_LEN * B_SZ)   /* 15360 word-level batch */

/* ---------------- persistent scratch (device globals; no allocs) ------------- */
__device__ float g_xe[T_LEN * NW * E_DIM];            /* 12.29M  */
__device__ float g_xw[2L * T_LEN * NW * (3 * HW)];    /* 69.12M; reused for sentence xw (needs 64.51M) */
__device__ float g_y0w[T_LEN * NW * (2 * HW)];        /* 23.04M  */
__device__ float g_words[NW * (4 * HW)];              /* 4.61M   */
__device__ float g_y0s[S_LEN * B_SZ * (2 * HS)];      /* 21.50M  */
__device__ float g_hw0a[2 * NW * HW], g_hw0b[2 * NW * HW];
__device__ float g_hw1a[2 * NW * HW], g_hw1b[2 * NW * HW];
__device__ float g_hs0a[2 * B_SZ * HS], g_hs0b[2 * B_SZ * HS];
__device__ float g_hs1a[2 * B_SZ * HS], g_hs1b[2 * B_SZ * HS];

/* ---------------- embedding gather: xe[t][n][e] = emb[x[s,t,b]][e] ----------- */
__global__ void embed_k(const int* __restrict__ x, const float* __restrict__ emb,
                        float* __restrict__ xe) {
    int idx = blockIdx.x * 256 + threadIdx.x;
    if (idx >= T_LEN * NW * E_DIM) return;
    int e = idx % E_DIM;
    int n = (idx / E_DIM) % NW;
    int t = idx / (E_DIM * NW);
    int s = n >> 7, b = n & 127;
    int tok = x[(s * T_LEN + t) * B_SZ + b];
    xe[idx] = emb[tok * E_DIM + e];
}

/* -------- C[m][g] = bias[g] + sum_k A[m,k]*W[g,k]   (A:MxK, W:GxK row-major) --
   128x128 tile, TK=8, 8x8 per thread, 256 threads. ------------------------- */
__global__ __launch_bounds__(256) void sgemm_nt_bias(
    const float* __restrict__ A, const float* __restrict__ W,
    const float* __restrict__ bias, float* __restrict__ C,
    int M, int G, int K)
{
    __shared__ float As[8][128];
    __shared__ float Ws[8][128];
    int tid = threadIdx.x;
    int tx = tid & 15, ty = tid >> 4;
    int row0 = blockIdx.y * 128, col0 = blockIdx.x * 128;

    float acc[8][8];
#pragma unroll
    for (int i = 0; i < 8; i++)
#pragma unroll
        for (int j = 0; j < 8; j++) acc[i][j] = 0.f;

    for (int k0 = 0; k0 < K; k0 += 8) {
#pragma unroll
        for (int j = 0; j < 4; j++) {
            int e = tid + j * 256;          /* 0..1023 */
            int r = e >> 3, kk = e & 7;
            int gk = k0 + kk;
            int gr = row0 + r;
            As[kk][r] = (gr < M && gk < K) ? A[(long)gr * K + gk] : 0.f;
            int gc = col0 + r;
            Ws[kk][r] = (gc < G && gk < K) ? W[(long)gc * K + gk] : 0.f;
        }
        __syncthreads();
#pragma unroll
        for (int kk = 0; kk < 8; kk++) {
            float4 a0 = *(const float4*)&As[kk][ty * 8];
            float4 a1 = *(const float4*)&As[kk][ty * 8 + 4];
            float4 b0 = *(const float4*)&Ws[kk][tx * 8];
            float4 b1 = *(const float4*)&Ws[kk][tx * 8 + 4];
            float a[8] = {a0.x, a0.y, a0.z, a0.w, a1.x, a1.y, a1.z, a1.w};
            float b[8] = {b0.x, b0.y, b0.z, b0.w, b1.x, b1.y, b1.z, b1.w};
#pragma unroll
            for (int i = 0; i < 8; i++)
#pragma unroll
                for (int j = 0; j < 8; j++) acc[i][j] += a[i] * b[j];
        }
        __syncthreads();
    }

#pragma unroll
    for (int i = 0; i < 8; i++) {
        int gr = row0 + ty * 8 + i;
        if (gr >= M) continue;
#pragma unroll
        for (int j = 0; j < 8; j++) {
            int gc = col0 + tx * 8 + j;
            if (gc < G) C[(long)gr * G + gc] = acc[i][j] + bias[gc];
        }
    }
}

/* -------- fused GRU step: gh = h@Whh^T + bhh, gate math, h_new write --------
   Rows = 2*Nb (dir-major). Block: 64 rows x 16 h-cols (x3 gates). 256 thr.
   xw layout [2][T][Nb][3H]; y (optional) [T][Nb][2H]. ----------------------- */
__global__ __launch_bounds__(256) void gru_step(
    const float* __restrict__ h_in, float* __restrict__ h_out,
    const float* __restrict__ xw, const float* __restrict__ Whh,
    const float* __restrict__ bhh, float* __restrict__ y,
    int H, int Nb, int T, int t_f, int t_b)
{
    __shared__ float As[16][64];
    __shared__ float Ws[3][16][16];
    int tid = threadIdx.x;
    int tx = tid & 15, ty = tid >> 4;
    int row0 = blockIdx.x * 64;
    int dir = row0 / Nb;              /* tiles never straddle dirs (Nb%64==0) */
    int n0 = row0 - dir * Nb;
    int h0 = blockIdx.y * 16;
    const float* Wd = Whh + (long)dir * 3 * H * H;
    const float* hin_d = h_in + ((long)dir * Nb + n0) * H;

    float accr[4] = {0.f, 0.f, 0.f, 0.f};
    float accz[4] = {0.f, 0.f, 0.f, 0.f};
    float accn[4] = {0.f, 0.f, 0.f, 0.f};

    for (int k0 = 0; k0 < H; k0 += 16) {
#pragma unroll
        for (int j = 0; j < 4; j++) {
            int e = tid + j * 256;        /* 0..1023: 64 rows x 16 k */
            int r = e >> 4, kk = e & 15;
            int gk = k0 + kk;
            As[kk][r] = (gk < H) ? hin_d[(long)r * H + gk] : 0.f;
        }
#pragma unroll
        for (int j = 0; j < 3; j++) {
            int e = tid + j * 256;        /* 0..767: 3 gates x 16 h x 16 k */
            int gate = e >> 8;
            int rem = e & 255;
            int hh = rem >> 4, kk = rem & 15;
            int gh_ = h0 + hh, gk = k0 + kk;
            Ws[gate][kk][hh] = (gh_ < H && gk < H)
                ? Wd[((long)gate * H + gh_) * H + gk] : 0.f;
        }
        __syncthreads();
#pragma unroll
        for (int kk = 0; kk < 16; kk++) {
            float wr = Ws[0][kk][tx], wz = Ws[1][kk][tx], wn = Ws[2][kk][tx];
#pragma unroll
            for (int i = 0; i < 4; i++) {
                float a = As[kk][ty * 4 + i];
                accr[i] += a * wr;
                accz[i] += a * wz;
                accn[i] += a * wn;
            }
        }
        __syncthreads();
    }

    int hc = h0 + tx;
    if (hc >= H) return;
    int t = dir ? t_b : t_f;
    float br = bhh[dir * 3 * H + hc];
    float bz = bhh[dir * 3 * H + H + hc];
    float bn = bhh[dir * 3 * H + 2 * H + hc];
#pragma unroll
    for (int i = 0; i < 4; i++) {
        int n = n0 + ty * 4 + i;
        long xb = ((long)(dir * T + t) * Nb + n) * (3 * H);
        float xr = xw[xb + hc];
        float xz = xw[xb + H + hc];
        float xn = xw[xb + 2 * H + hc];
        float gr = accr[i] + br, gz = accz[i] + bz, gn = accn[i] + bn;
        float rg = 1.f / (1.f + expf(-(xr + gr)));
        float zg = 1.f / (1.f + expf(-(xz + gz)));
        float ng = tanhf(xn + rg * gn);
        long hidx = ((long)dir * Nb + n) * H + hc;
        float ho = h_in[hidx];
        float hn = (1.f - zg) * ng + zg * ho;
        h_out[hidx] = hn;
        if (y) y[((long)t * Nb + n) * 2 * H + (long)dir * H + hc] = hn;
    }
}

/* ---- concat [hf0|hb0|hf1|hb1] into rows ------------------------------------ */
__global__ void concat4_k(const float* __restrict__ h0f, const float* __restrict__ h1f,
                          float* __restrict__ out, int Nrows, int H) {
    int idx = blockIdx.x * 256 + threadIdx.x;
    int C = 4 * H;
    if (idx >= Nrows * C) return;
    int c = idx % C;
    int n = idx / C;
    float v;
    if (c < 2 * H) {
        int d = c / H, hh = c % H;
        v = h0f[((long)d * Nrows + n) * H + hh];
    } else {
        int c2 = c - 2 * H;
        int d = c2 / H, hh = c2 % H;
        v = h1f[((long)d * Nrows + n) * H + hh];
    }
    out[idx] = v;
}

/* ---------------------------------- host ------------------------------------ */
extern "C" void kernel_launch(void* const* d_in, const int* in_sizes, int n_in,
                              void* d_out, int out_size) {
    const int*   x        = (const int*)  d_in[0];
    const float* emb      = (const float*)d_in[1];
    const float* we_Wih0  = (const float*)d_in[2];
    const float* we_Whh0  = (const float*)d_in[3];
    const float* we_bih0  = (const float*)d_in[4];
    const float* we_bhh0  = (const float*)d_in[5];
    const float* we_Wih1  = (const float*)d_in[6];
    const float* we_Whh1  = (const float*)d_in[7];
    const float* we_bih1  = (const float*)d_in[8];
    const float* we_bhh1  = (const float*)d_in[9];
    const float* se_Wih0  = (const float*)d_in[10];
    const float* se_Whh0  = (const float*)d_in[11];
    const float* se_bih0  = (const float*)d_in[12];
    const float* se_bhh0  = (const float*)d_in[13];
    const float* se_Wih1  = (const float*)d_in[14];
    const float* se_Whh1  = (const float*)d_in[15];
    const float* se_bih1  = (const float*)d_in[16];
    const float* se_bhh1  = (const float*)d_in[17];
    (void)in_sizes; (void)n_in; (void)out_size;

    float *xe, *xw, *y0w, *words, *y0s;
    float *hw0a, *hw0b, *hw1a, *hw1b, *hs0a, *hs0b, *hs1a, *hs1b;
    cudaGetSymbolAddress((void**)&xe,    g_xe);
    cudaGetSymbolAddress((void**)&xw,    g_xw);
    cudaGetSymbolAddress((void**)&y0w,   g_y0w);
    cudaGetSymbolAddress((void**)&words, g_words);
    cudaGetSymbolAddress((void**)&y0s,   g_y0s);
    cudaGetSymbolAddress((void**)&hw0a,  g_hw0a);
    cudaGetSymbolAddress((void**)&hw0b,  g_hw0b);
    cudaGetSymbolAddress((void**)&hw1a,  g_hw1a);
    cudaGetSymbolAddress((void**)&hw1b,  g_hw1b);
    cudaGetSymbolAddress((void**)&hs0a,  g_hs0a);
    cudaGetSymbolAddress((void**)&hs0b,  g_hs0b);
    cudaGetSymbolAddress((void**)&hs1a,  g_hs1a);
    cudaGetSymbolAddress((void**)&hs1b,  g_hs1b);

    /* 1. embedding */
    {
        int tot = T_LEN * NW * E_DIM;
        embed_k<<<(tot + 255) / 256, 256>>>(x, emb, xe);
    }

    /* 2. word layer0: xw precompute + 10 recurrent steps (ys -> y0w) */
    for (int d = 0; d < 2; d++) {
        dim3 g((3 * HW + 127) / 128, (T_LEN * NW + 127) / 128);
        sgemm_nt_bias<<<g, 256>>>(xe, we_Wih0 + (long)d * 3 * HW * E_DIM,
                                  we_bih0 + d * 3 * HW,
                                  xw + (long)d * T_LEN * NW * 3 * HW,
                                  T_LEN * NW, 3 * HW, E_DIM);
    }
    cudaMemsetAsync(hw0a, 0, sizeof(float) * 2 * NW * HW);
    {
        dim3 grid(2 * NW / 64, (HW + 15) / 16);
        for (int s = 0; s < T_LEN; s++) {
            const float* hi = (s & 1) ? hw0b : hw0a;
            float*       ho = (s & 1) ? hw0a : hw0b;
            gru_step<<<grid, 256>>>(hi, ho, xw, we_Whh0, we_bhh0, y0w,
                                    HW, NW, T_LEN, s, T_LEN - 1 - s);
        }
    }
    /* final hidden of layer0 in hw0a (10 steps -> even) */

    /* 3. word layer1: xw from y0w + 10 steps (no ys) */
    for (int d = 0; d < 2; d++) {
        dim3 g((3 * HW + 127) / 128, (T_LEN * NW + 127) / 128);
        sgemm_nt_bias<<<g, 256>>>(y0w, we_Wih1 + (long)d * 3 * HW * 2 * HW,
                                  we_bih1 + d * 3 * HW,
                                  xw + (long)d * T_LEN * NW * 3 * HW,
                                  T_LEN * NW, 3 * HW, 2 * HW);
    }
    cudaMemsetAsync(hw1a, 0, sizeof(float) * 2 * NW * HW);
    {
        dim3 grid(2 * NW / 64, (HW + 15) / 16);
        for (int s = 0; s < T_LEN; s++) {
            const float* hi = (s & 1) ? hw1b : hw1a;
            float*       ho = (s & 1) ? hw1a : hw1b;
            gru_step<<<grid, 256>>>(hi, ho, xw, we_Whh1, we_bhh1, (float*)0,
                                    HW, NW, T_LEN, s, T_LEN - 1 - s);
        }
    }

    /* 4. words = [hf0|hb0|hf1|hb1] : [NW, 300] (rows = s*128+b) */
    concat4_k<<<(NW * 4 * HW + 255) / 256, 256>>>(hw0a, hw1a, words, NW, HW);

    /* 5. sentence layer0: xw precompute + 120 steps (ys -> y0s) */
    for (int d = 0; d < 2; d++) {
        dim3 g((3 * HS + 127) / 128, (S_LEN * B_SZ + 127) / 128);
        sgemm_nt_bias<<<g, 256>>>(words, se_Wih0 + (long)d * 3 * HS * 4 * HW,
                                  se_bih0 + d * 3 * HS,
                                  xw + (long)d * S_LEN * B_SZ * 3 * HS,
                                  S_LEN * B_SZ, 3 * HS, 4 * HW);
    }
    cudaMemsetAsync(hs0a, 0, sizeof(float) * 2 * B_SZ * HS);
    {
        dim3 grid(2 * B_SZ / 64, (HS + 15) / 16);
        for (int s = 0; s < S_LEN; s++) {
            const float* hi = (s & 1) ? hs0b : hs0a;
            float*       ho = (s & 1) ? hs0a : hs0b;
            gru_step<<<grid, 256>>>(hi, ho, xw, se_Whh0, se_bhh0, y0s,
                                    HS, B_SZ, S_LEN, s, S_LEN - 1 - s);
        }
    }
    /* final in hs0a (120 steps -> even) */

    /* 6. sentence layer1: xw from y0s + 120 steps (no ys) */
    for (int d = 0; d < 2; d++) {
        dim3 g((3 * HS + 127) / 128, (S_LEN * B_SZ + 127) / 128);
        sgemm_nt_bias<<<g, 256>>>(y0s, se_Wih1 + (long)d * 3 * HS * 2 * HS,
                                  se_bih1 + d * 3 * HS,
                                  xw + (long)d * S_LEN * B_SZ * 3 * HS,
                                  S_LEN * B_SZ, 3 * HS, 2 * HS);
    }
    cudaMemsetAsync(hs1a, 0, sizeof(float) * 2 * B_SZ * HS);
    {
        dim3 grid(2 * B_SZ / 64, (HS + 15) / 16);
        for (int s = 0; s < S_LEN; s++) {
            const float* hi = (s & 1) ? hs1b : hs1a;
            float*       ho = (s & 1) ? hs1a : hs1b;
            gru_step<<<grid, 256>>>(hi, ho, xw, se_Whh1, se_bhh1, (float*)0,
                                    HS, B_SZ, S_LEN, s, S_LEN - 1 - s);
        }
    }

    /* 7. output [1, 128, 2800] = [sf0|sb0|sf1|sb1] per batch row */
    concat4_k<<<(B_SZ * 4 * HS + 255) / 256, 256>>>(hs0a, hs1a, (float*)d_out,
                                                    B_SZ, HS);
}

// round 4
// speedup vs baseline: 1.4964x; 1.4964x over previous
#include <cuda_runtime.h>
#include <math.h>

#define S_LEN 120
#define T_LEN 10
#define B_SZ  128
#define E_DIM 80
#define HW    75
#define HS    700
#define NW    (S_LEN * B_SZ)   /* 15360 word-level batch */

/* ---------------- persistent scratch (device globals; no allocs) ------------- */
__device__ float g_xe[T_LEN * NW * E_DIM];
__device__ float g_xw[2L * T_LEN * NW * (3 * HW)];    /* reused for sentence xw */
__device__ float g_y0w[T_LEN * NW * (2 * HW)];
__device__ float g_words[NW * (4 * HW)];
__device__ float g_y0s[S_LEN * B_SZ * (2 * HS)];
__device__ float g_hw0a[2 * NW * HW], g_hw0b[2 * NW * HW];
__device__ float g_hw1a[2 * NW * HW], g_hw1b[2 * NW * HW];
__device__ float g_hs0a[2 * B_SZ * HS], g_hs0b[2 * B_SZ * HS];
__device__ float g_hs1a[2 * B_SZ * HS], g_hs1b[2 * B_SZ * HS];

/* ---------------- tf32 helpers ---------------------------------------------- */
__device__ __forceinline__ unsigned f2tf(float x) {
    unsigned r; asm("cvt.rna.tf32.f32 %0, %1;" : "=r"(r) : "f"(x)); return r;
}
__device__ __forceinline__ void tf32_split(float x, unsigned &b, unsigned &s) {
    b = f2tf(x);
    s = f2tf(x - __uint_as_float(b));
}
__device__ __forceinline__ void mma8(float d[4],
    unsigned a0, unsigned a1, unsigned a2, unsigned a3,
    unsigned b0, unsigned b1)
{
    asm volatile(
        "mma.sync.aligned.m16n8k8.row.col.f32.tf32.tf32.f32 "
        "{%0,%1,%2,%3},{%4,%5,%6,%7},{%8,%9},{%0,%1,%2,%3};"
        : "+f"(d[0]), "+f"(d[1]), "+f"(d[2]), "+f"(d[3])
        : "r"(a0), "r"(a1), "r"(a2), "r"(a3), "r"(b0), "r"(b1));
}

/* ---------------- embedding gather ------------------------------------------ */
__global__ void embed_k(const int* __restrict__ x, const float* __restrict__ emb,
                        float* __restrict__ xe) {
    int idx = blockIdx.x * 256 + threadIdx.x;
    if (idx >= T_LEN * NW * E_DIM) return;
    int e = idx % E_DIM;
    int n = (idx / E_DIM) % NW;
    int t = idx / (E_DIM * NW);
    int s = n >> 7, b = n & 127;
    int tok = x[(s * T_LEN + t) * B_SZ + b];
    xe[idx] = emb[tok * E_DIM + e];
}

/* -------- C[m][g] = bias[g] + sum_k A[m,k]*W[g,k]  via split-tf32 mma --------
   Block tile 128x64, BK=16, 8 warps (4x2). Per warp: 32x32 = 2x4 mma tiles. */
__global__ __launch_bounds__(256) void mma_gemm_bias(
    const float* __restrict__ A, const float* __restrict__ W,
    const float* __restrict__ bias, float* __restrict__ C,
    int M, int G, int K)
{
    __shared__ float As[128][20];
    __shared__ float Ws[64][20];
    int tid = threadIdx.x;
    int lane = tid & 31, wid = tid >> 5;
    int gid = lane >> 2, tig = lane & 3;
    int wm = wid & 3, wn = wid >> 2;
    int row0 = blockIdx.y * 128, col0 = blockIdx.x * 64;

    float acc[2][4][4];
#pragma unroll
    for (int mt = 0; mt < 2; mt++)
#pragma unroll
        for (int nt = 0; nt < 4; nt++)
#pragma unroll
            for (int i = 0; i < 4; i++) acc[mt][nt][i] = 0.f;

    int iters = (K + 15) >> 4;
    for (int it = 0; it < iters; it++) {
        int k0 = it << 4;
#pragma unroll
        for (int j = 0; j < 8; j++) {
            int e = tid + j * 256;
            int r = e >> 4, kk = e & 15;
            int gk = k0 + kk, gr = row0 + r;
            As[r][kk] = (gk < K && gr < M) ? A[(long)gr * K + gk] : 0.f;
        }
#pragma unroll
        for (int j = 0; j < 4; j++) {
            int e = tid + j * 256;
            int r = e >> 4, kk = e & 15;
            int gk = k0 + kk, gc = col0 + r;
            Ws[r][kk] = (gk < K && gc < G) ? W[(long)gc * K + gk] : 0.f;
        }
        __syncthreads();
#pragma unroll
        for (int ks = 0; ks < 16; ks += 8) {
            unsigned ab[2][4], asm_[2][4];
#pragma unroll
            for (int mt = 0; mt < 2; mt++) {
                int mr = wm * 32 + mt * 16;
                tf32_split(As[mr + gid    ][ks + tig    ], ab[mt][0], asm_[mt][0]);
                tf32_split(As[mr + gid + 8][ks + tig    ], ab[mt][1], asm_[mt][1]);
                tf32_split(As[mr + gid    ][ks + tig + 4], ab[mt][2], asm_[mt][2]);
                tf32_split(As[mr + gid + 8][ks + tig + 4], ab[mt][3], asm_[mt][3]);
            }
#pragma unroll
            for (int nt = 0; nt < 4; nt++) {
                int nr = wn * 32 + nt * 8 + gid;
                unsigned bb0, bs0, bb1, bs1;
                tf32_split(Ws[nr][ks + tig    ], bb0, bs0);
                tf32_split(Ws[nr][ks + tig + 4], bb1, bs1);
#pragma unroll
                for (int mt = 0; mt < 2; mt++) {
                    mma8(acc[mt][nt], ab[mt][0], ab[mt][1], ab[mt][2], ab[mt][3], bb0, bb1);
                    mma8(acc[mt][nt], ab[mt][0], ab[mt][1], ab[mt][2], ab[mt][3], bs0, bs1);
                    mma8(acc[mt][nt], asm_[mt][0], asm_[mt][1], asm_[mt][2], asm_[mt][3], bb0, bb1);
                }
            }
        }
        __syncthreads();
    }
#pragma unroll
    for (int mt = 0; mt < 2; mt++)
#pragma unroll
        for (int nt = 0; nt < 4; nt++)
#pragma unroll
            for (int i = 0; i < 4; i++) {
                int gr = row0 + wm * 32 + mt * 16 + gid + 8 * (i >> 1);
                int gc = col0 + wn * 32 + nt * 8 + tig * 2 + (i & 1);
                if (gr < M && gc < G)
                    C[(long)gr * G + gc] = acc[mt][nt][i] + bias[gc];
            }
}

/* -------- fused GRU step via split-tf32 mma ---------------------------------
   Block: 64 rows x (3 gates x 16 hc) = 64x48 output, 4 warps (1 m-tile each,
   6 n-tiles). Epilogue: gate triple for (row,hc) lands in the same thread
   because gate boundaries (16 cols) align with n-tile pairs (2x8). --------- */
__global__ __launch_bounds__(128) void gru_step_mma(
    const float* __restrict__ h_in, float* __restrict__ h_out,
    const float* __restrict__ xw, const float* __restrict__ Whh,
    const float* __restrict__ bhh, float* __restrict__ y,
    int H, int Nb, int T, int t_f, int t_b)
{
    __shared__ float Hs[64][20];
    __shared__ float Ws[48][20];
    int tid = threadIdx.x;
    int lane = tid & 31, wid = tid >> 5;
    int gid = lane >> 2, tig = lane & 3;
    int r0 = blockIdx.x * 64;
    int dir = r0 / Nb;                 /* tiles never straddle dirs (Nb%64==0) */
    int n0 = r0 - dir * Nb;
    int h0 = blockIdx.y * 16;
    const float* Wd = Whh + (long)dir * 3 * H * H;
    const float* hin_d = h_in + ((long)dir * Nb + n0) * H;

    float acc[6][4];
#pragma unroll
    for (int nt = 0; nt < 6; nt++)
#pragma unroll
        for (int i = 0; i < 4; i++) acc[nt][i] = 0.f;

    int iters = (H + 15) >> 4;
    for (int it = 0; it < iters; it++) {
        int k0 = it << 4;
#pragma unroll
        for (int j = 0; j < 8; j++) {
            int e = tid + j * 128;
            int r = e >> 4, kk = e & 15;
            int gk = k0 + kk;
            Hs[r][kk] = (gk < H) ? hin_d[(long)r * H + gk] : 0.f;
        }
#pragma unroll
        for (int j = 0; j < 6; j++) {
            int e = tid + j * 128;
            int r = e >> 4, kk = e & 15;       /* r: 0..47 */
            int gate = r >> 4, hh = r & 15;
            int gk = k0 + kk;
            Ws[r][kk] = (gk < H && (h0 + hh) < H)
                ? Wd[((long)gate * H + h0 + hh) * H + gk] : 0.f;
        }
        __syncthreads();
#pragma unroll
        for (int ks = 0; ks < 16; ks += 8) {
            int mr = wid * 16;
            unsigned ab[4], as_[4];
            tf32_split(Hs[mr + gid    ][ks + tig    ], ab[0], as_[0]);
            tf32_split(Hs[mr + gid + 8][ks + tig    ], ab[1], as_[1]);
            tf32_split(Hs[mr + gid    ][ks + tig + 4], ab[2], as_[2]);
            tf32_split(Hs[mr + gid + 8][ks + tig + 4], ab[3], as_[3]);
#pragma unroll
            for (int nt = 0; nt < 6; nt++) {
                unsigned bb0, bs0, bb1, bs1;
                tf32_split(Ws[nt * 8 + gid][ks + tig    ], bb0, bs0);
                tf32_split(Ws[nt * 8 + gid][ks + tig + 4], bb1, bs1);
                mma8(acc[nt], ab[0], ab[1], ab[2], ab[3], bb0, bb1);
                mma8(acc[nt], ab[0], ab[1], ab[2], ab[3], bs0, bs1);
                mma8(acc[nt], as_[0], as_[1], as_[2], as_[3], bb0, bb1);
            }
        }
        __syncthreads();
    }

    int t = dir ? t_b : t_f;
#pragma unroll
    for (int nt = 0; nt < 2; nt++)
#pragma unroll
        for (int i = 0; i < 4; i++) {
            int n = n0 + wid * 16 + gid + 8 * (i >> 1);
            int hc = h0 + nt * 8 + tig * 2 + (i & 1);
            if (hc >= H) continue;
            float br = bhh[dir * 3 * H + hc];
            float bz = bhh[dir * 3 * H + H + hc];
            float bn = bhh[dir * 3 * H + 2 * H + hc];
            long xb = ((long)(dir * T + t) * Nb + n) * (3 * H);
            float xr = xw[xb + hc];
            float xz = xw[xb + H + hc];
            float xn = xw[xb + 2 * H + hc];
            float gr_ = acc[nt][i] + br;
            float gz_ = acc[nt + 2][i] + bz;
            float gn_ = acc[nt + 4][i] + bn;
            float rg = 1.f / (1.f + expf(-(xr + gr_)));
            float zg = 1.f / (1.f + expf(-(xz + gz_)));
            float ng = tanhf(xn + rg * gn_);
            long hidx = ((long)dir * Nb + n) * H + hc;
            float hp = h_in[hidx];
            float hn = (1.f - zg) * ng + zg * hp;
            h_out[hidx] = hn;
            if (y) y[((long)t * Nb + n) * 2 * H + (long)dir * H + hc] = hn;
        }
}

/* ---- concat [hf0|hb0|hf1|hb1] into rows ------------------------------------ */
__global__ void concat4_k(const float* __restrict__ h0f, const float* __restrict__ h1f,
                          float* __restrict__ out, int Nrows, int H) {
    int idx = blockIdx.x * 256 + threadIdx.x;
    int C = 4 * H;
    if (idx >= Nrows * C) return;
    int c = idx % C;
    int n = idx / C;
    float v;
    if (c < 2 * H) {
        int d = c / H, hh = c % H;
        v = h0f[((long)d * Nrows + n) * H + hh];
    } else {
        int c2 = c - 2 * H;
        int d = c2 / H, hh = c2 % H;
        v = h1f[((long)d * Nrows + n) * H + hh];
    }
    out[idx] = v;
}

/* ---------------------------------- host ------------------------------------ */
extern "C" void kernel_launch(void* const* d_in, const int* in_sizes, int n_in,
                              void* d_out, int out_size) {
    const int*   x        = (const int*)  d_in[0];
    const float* emb      = (const float*)d_in[1];
    const float* we_Wih0  = (const float*)d_in[2];
    const float* we_Whh0  = (const float*)d_in[3];
    const float* we_bih0  = (const float*)d_in[4];
    const float* we_bhh0  = (const float*)d_in[5];
    const float* we_Wih1  = (const float*)d_in[6];
    const float* we_Whh1  = (const float*)d_in[7];
    const float* we_bih1  = (const float*)d_in[8];
    const float* we_bhh1  = (const float*)d_in[9];
    const float* se_Wih0  = (const float*)d_in[10];
    const float* se_Whh0  = (const float*)d_in[11];
    const float* se_bih0  = (const float*)d_in[12];
    const float* se_bhh0  = (const float*)d_in[13];
    const float* se_Wih1  = (const float*)d_in[14];
    const float* se_Whh1  = (const float*)d_in[15];
    const float* se_bih1  = (const float*)d_in[16];
    const float* se_bhh1  = (const float*)d_in[17];
    (void)in_sizes; (void)n_in; (void)out_size;

    float *xe, *xw, *y0w, *words, *y0s;
    float *hw0a, *hw0b, *hw1a, *hw1b, *hs0a, *hs0b, *hs1a, *hs1b;
    cudaGetSymbolAddress((void**)&xe,    g_xe);
    cudaGetSymbolAddress((void**)&xw,    g_xw);
    cudaGetSymbolAddress((void**)&y0w,   g_y0w);
    cudaGetSymbolAddress((void**)&words, g_words);
    cudaGetSymbolAddress((void**)&y0s,   g_y0s);
    cudaGetSymbolAddress((void**)&hw0a,  g_hw0a);
    cudaGetSymbolAddress((void**)&hw0b,  g_hw0b);
    cudaGetSymbolAddress((void**)&hw1a,  g_hw1a);
    cudaGetSymbolAddress((void**)&hw1b,  g_hw1b);
    cudaGetSymbolAddress((void**)&hs0a,  g_hs0a);
    cudaGetSymbolAddress((void**)&hs0b,  g_hs0b);
    cudaGetSymbolAddress((void**)&hs1a,  g_hs1a);
    cudaGetSymbolAddress((void**)&hs1b,  g_hs1b);

    /* 1. embedding */
    {
        int tot = T_LEN * NW * E_DIM;
        embed_k<<<(tot + 255) / 256, 256>>>(x, emb, xe);
    }

    /* 2. word layer0: xw precompute + 10 recurrent steps (ys -> y0w) */
    for (int d = 0; d < 2; d++) {
        dim3 g((3 * HW + 63) / 64, (T_LEN * NW + 127) / 128);
        mma_gemm_bias<<<g, 256>>>(xe, we_Wih0 + (long)d * 3 * HW * E_DIM,
                                  we_bih0 + d * 3 * HW,
                                  xw + (long)d * T_LEN * NW * 3 * HW,
                                  T_LEN * NW, 3 * HW, E_DIM);
    }
    cudaMemsetAsync(hw0a, 0, sizeof(float) * 2 * NW * HW);
    {
        dim3 grid(2 * NW / 64, (HW + 15) / 16);
        for (int s = 0; s < T_LEN; s++) {
            const float* hi = (s & 1) ? hw0b : hw0a;
            float*       ho = (s & 1) ? hw0a : hw0b;
            gru_step_mma<<<grid, 128>>>(hi, ho, xw, we_Whh0, we_bhh0, y0w,
                                        HW, NW, T_LEN, s, T_LEN - 1 - s);
        }
    }

    /* 3. word layer1: xw from y0w + 10 steps (no ys) */
    for (int d = 0; d < 2; d++) {
        dim3 g((3 * HW + 63) / 64, (T_LEN * NW + 127) / 128);
        mma_gemm_bias<<<g, 256>>>(y0w, we_Wih1 + (long)d * 3 * HW * 2 * HW,
                                  we_bih1 + d * 3 * HW,
                                  xw + (long)d * T_LEN * NW * 3 * HW,
                                  T_LEN * NW, 3 * HW, 2 * HW);
    }
    cudaMemsetAsync(hw1a, 0, sizeof(float) * 2 * NW * HW);
    {
        dim3 grid(2 * NW / 64, (HW + 15) / 16);
        for (int s = 0; s < T_LEN; s++) {
            const float* hi = (s & 1) ? hw1b : hw1a;
            float*       ho = (s & 1) ? hw1a : hw1b;
            gru_step_mma<<<grid, 128>>>(hi, ho, xw, we_Whh1, we_bhh1, (float*)0,
                                        HW, NW, T_LEN, s, T_LEN - 1 - s);
        }
    }

    /* 4. words = [hf0|hb0|hf1|hb1] : [NW, 300] */
    concat4_k<<<(NW * 4 * HW + 255) / 256, 256>>>(hw0a, hw1a, words, NW, HW);

    /* 5. sentence layer0: xw precompute + 120 steps (ys -> y0s) */
    for (int d = 0; d < 2; d++) {
        dim3 g((3 * HS + 63) / 64, (S_LEN * B_SZ + 127) / 128);
        mma_gemm_bias<<<g, 256>>>(words, se_Wih0 + (long)d * 3 * HS * 4 * HW,
                                  se_bih0 + d * 3 * HS,
                                  xw + (long)d * S_LEN * B_SZ * 3 * HS,
                                  S_LEN * B_SZ, 3 * HS, 4 * HW);
    }
    cudaMemsetAsync(hs0a, 0, sizeof(float) * 2 * B_SZ * HS);
    {
        dim3 grid(2 * B_SZ / 64, (HS + 15) / 16);
        for (int s = 0; s < S_LEN; s++) {
            const float* hi = (s & 1) ? hs0b : hs0a;
            float*       ho = (s & 1) ? hs0a : hs0b;
            gru_step_mma<<<grid, 128>>>(hi, ho, xw, se_Whh0, se_bhh0, y0s,
                                        HS, B_SZ, S_LEN, s, S_LEN - 1 - s);
        }
    }

    /* 6. sentence layer1: xw from y0s + 120 steps (no ys) */
    for (int d = 0; d < 2; d++) {
        dim3 g((3 * HS + 63) / 64, (S_LEN * B_SZ + 127) / 128);
        mma_gemm_bias<<<g, 256>>>(y0s, se_Wih1 + (long)d * 3 * HS * 2 * HS,
                                  se_bih1 + d * 3 * HS,
                                  xw + (long)d * S_LEN * B_SZ * 3 * HS,
                                  S_LEN * B_SZ, 3 * HS, 2 * HS);
    }
    cudaMemsetAsync(hs1a, 0, sizeof(float) * 2 * B_SZ * HS);
    {
        dim3 grid(2 * B_SZ / 64, (HS + 15) / 16);
        for (int s = 0; s < S_LEN; s++) {
            const float* hi = (s & 1) ? hs1b : hs1a;
            float*       ho = (s & 1) ? hs1a : hs1b;
            gru_step_mma<<<grid, 128>>>(hi, ho, xw, se_Whh1, se_bhh1, (float*)0,
                                        HS, B_SZ, S_LEN, s, S_LEN - 1 - s);
        }
    }

    /* 7. output [1, 128, 2800] = [sf0|sb0|sf1|sb1] per batch row */
    concat4_k<<<(B_SZ * 4 * HS + 255) / 256, 256>>>(hs0a, hs1a, (float*)d_out,
                                                    B_SZ, HS);
}

// round 6
// speedup vs baseline: 1.7105x; 1.1431x over previous
#include <cuda_runtime.h>
#include <cuda_bf16.h>
#include <math.h>

#define S_LEN 120
#define T_LEN 10
#define B_SZ  128
#define E_DIM 80
#define HW    75
#define HWP   76
#define HS    700
#define NW    (S_LEN * B_SZ)   /* 15360 word-level batch */

typedef __nv_bfloat16 bf;

#define XE_N    (T_LEN * NW * E_DIM)
#define XW_N    (2L * T_LEN * NW * (3 * HW))   /* 69.12M fp32; sentence reuse needs 64.51M */
#define Y0W_N   (T_LEN * NW * 2 * HW)
#define WORDS_N (NW * 4 * HW)
#define Y0S_N   ((long)S_LEN * B_SZ * 2 * HS)
#define HWBUF_N (2 * NW * HWP)
#define HSBUF_N (2 * B_SZ * HS)

/* ---------------- persistent scratch (device globals; no allocs) ------------- */
__device__ bf    g_xe_b[XE_N],    g_xe_s[XE_N];
__device__ float g_xw[XW_N];
__device__ bf    g_y0w_b[Y0W_N],  g_y0w_s[Y0W_N];
__device__ bf    g_words_b[WORDS_N], g_words_s[WORDS_N];
__device__ bf    g_y0s_b[Y0S_N],  g_y0s_s[Y0S_N];
__device__ float g_hwf[4][HWBUF_N];
__device__ bf    g_hwb[4][HWBUF_N], g_hws[4][HWBUF_N];
__device__ float g_hsf[4][HSBUF_N];
__device__ bf    g_hsb[4][HSBUF_N], g_hss[4][HSBUF_N];
/* weight splits */
__device__ bf g_weWih0_b[2*3*HW*E_DIM],  g_weWih0_s[2*3*HW*E_DIM];
__device__ bf g_weWih1_b[2*3*HW*2*HW],   g_weWih1_s[2*3*HW*2*HW];
__device__ bf g_weWhh0_b[2*3*HW*HWP],    g_weWhh0_s[2*3*HW*HWP];
__device__ bf g_weWhh1_b[2*3*HW*HWP],    g_weWhh1_s[2*3*HW*HWP];
__device__ bf g_seWih0_b[2*3*HS*4*HW],   g_seWih0_s[2*3*HS*4*HW];
__device__ bf g_seWih1_b[2*3*HS*2*HS],   g_seWih1_s[2*3*HS*2*HS];
__device__ bf g_seWhh0_b[2*3*HS*HS],     g_seWhh0_s[2*3*HS*HS];
__device__ bf g_seWhh1_b[2*3*HS*HS],     g_seWhh1_s[2*3*HS*HS];

/* ---------------- helpers ---------------------------------------------------- */
__device__ __forceinline__ void bsplit(float v, bf &b, bf &s) {
    b = __float2bfloat16_rn(v);
    s = __float2bfloat16_rn(v - __bfloat162float(b));
}
__device__ __forceinline__ void mma16(float d[4], const unsigned a[4],
                                      unsigned b0, unsigned b1) {
    asm volatile(
        "mma.sync.aligned.m16n8k16.row.col.f32.bf16.bf16.f32 "
        "{%0,%1,%2,%3},{%4,%5,%6,%7},{%8,%9},{%0,%1,%2,%3};"
        : "+f"(d[0]), "+f"(d[1]), "+f"(d[2]), "+f"(d[3])
        : "r"(a[0]), "r"(a[1]), "r"(a[2]), "r"(a[3]), "r"(b0), "r"(b1));
}

/* ---------------- weight split: fp32 [rows,K] -> bf16 big/small [rows,KP] ---- */
__global__ void split_k(const float* __restrict__ W, bf* __restrict__ b,
                        bf* __restrict__ s, int rows, int K, int KP) {
    long idx = blockIdx.x * 256L + threadIdx.x;
    if (idx >= (long)rows * KP) return;
    int k = (int)(idx % KP);
    long r = idx / KP;
    float v = (k < K) ? W[r * K + k] : 0.f;
    bf vb, vs; bsplit(v, vb, vs);
    b[idx] = vb; s[idx] = vs;
}

/* ---------------- embedding gather + split ----------------------------------- */
__global__ void embed_split_k(const int* __restrict__ x, const float* __restrict__ emb,
                              bf* __restrict__ xb, bf* __restrict__ xs) {
    long idx = blockIdx.x * 256L + threadIdx.x;
    if (idx >= XE_N) return;
    int e = (int)(idx % E_DIM);
    int n = (int)((idx / E_DIM) % NW);
    int t = (int)(idx / ((long)E_DIM * NW));
    int s = n >> 7, bb_ = n & 127;
    int tok = x[(s * T_LEN + t) * B_SZ + bb_];
    float v = emb[(long)tok * E_DIM + e];
    bf vb, vs; bsplit(v, vb, vs);
    xb[idx] = vb; xs[idx] = vs;
}

/* -------- C[m][g] = bias[g] + A[m,:]·W[g,:]  via bf16 3-mma split ------------
   A,W pre-split bf16 (K even). Tile 128x64, BK=32, 256 thr, 8 warps (4x2).
   Register-staged pipeline hides global latency. ---------------------------- */
__global__ __launch_bounds__(256) void mma_gemm_bias(
    const bf* __restrict__ Ag_b, const bf* __restrict__ Ag_s,
    const bf* __restrict__ Wg_b, const bf* __restrict__ Wg_s,
    const float* __restrict__ bias, float* __restrict__ C,
    int M, int G, int K)
{
    __shared__ __align__(16) bf Asm[2][128][36];
    __shared__ __align__(16) bf Wsm[2][64][36];
    int tid = threadIdx.x, lane = tid & 31, wid = tid >> 5;
    int gid = lane >> 2, tig = lane & 3;
    int wm = wid & 3, wn = wid >> 2;
    int row0 = blockIdx.y * 128, col0 = blockIdx.x * 64;

    float acc[2][4][4];
#pragma unroll
    for (int mt = 0; mt < 2; mt++)
#pragma unroll
        for (int nt = 0; nt < 4; nt++)
#pragma unroll
            for (int i = 0; i < 4; i++) acc[mt][nt][i] = 0.f;

    unsigned pa[2][8], pw[2][4];
    auto fetch = [&](int k0) {
#pragma unroll
        for (int j = 0; j < 8; j++) {
            int e = tid + j * 256, r = e >> 4, kk = e & 15;
            int gk = k0 + 2 * kk, gr = row0 + r;
            bool v = (gk < K) && (gr < M);
            long off = (long)gr * K + gk;
            pa[0][j] = v ? *(const unsigned*)(Ag_b + off) : 0u;
            pa[1][j] = v ? *(const unsigned*)(Ag_s + off) : 0u;
        }
#pragma unroll
        for (int j = 0; j < 4; j++) {
            int e = tid + j * 256, r = e >> 4, kk = e & 15;
            int gk = k0 + 2 * kk, gc = col0 + r;
            bool v = (gk < K) && (gc < G);
            long off = (long)gc * K + gk;
            pw[0][j] = v ? *(const unsigned*)(Wg_b + off) : 0u;
            pw[1][j] = v ? *(const unsigned*)(Wg_s + off) : 0u;
        }
    };
    fetch(0);
    for (int k0 = 0; k0 < K; k0 += 32) {
#pragma unroll
        for (int j = 0; j < 8; j++) {
            int e = tid + j * 256, r = e >> 4, kk = e & 15;
            ((unsigned*)Asm[0][r])[kk] = pa[0][j];
            ((unsigned*)Asm[1][r])[kk] = pa[1][j];
        }
#pragma unroll
        for (int j = 0; j < 4; j++) {
            int e = tid + j * 256, r = e >> 4, kk = e & 15;
            ((unsigned*)Wsm[0][r])[kk] = pw[0][j];
            ((unsigned*)Wsm[1][r])[kk] = pw[1][j];
        }
        __syncthreads();
        if (k0 + 32 < K) fetch(k0 + 32);
#pragma unroll
        for (int half = 0; half < 2; half++) {
            int base = half * 8;
            unsigned ab[2][4], as_[2][4];
#pragma unroll
            for (int mt = 0; mt < 2; mt++) {
                int mr = wm * 32 + mt * 16;
                const unsigned* p0b = (const unsigned*)Asm[0][mr + gid];
                const unsigned* p1b = (const unsigned*)Asm[0][mr + gid + 8];
                const unsigned* p0s = (const unsigned*)Asm[1][mr + gid];
                const unsigned* p1s = (const unsigned*)Asm[1][mr + gid + 8];
                ab[mt][0] = p0b[base + tig];     ab[mt][1] = p1b[base + tig];
                ab[mt][2] = p0b[base + tig + 4]; ab[mt][3] = p1b[base + tig + 4];
                as_[mt][0] = p0s[base + tig];     as_[mt][1] = p1s[base + tig];
                as_[mt][2] = p0s[base + tig + 4]; as_[mt][3] = p1s[base + tig + 4];
            }
#pragma unroll
            for (int nt = 0; nt < 4; nt++) {
                int nr = wn * 32 + nt * 8 + gid;
                const unsigned* pb = (const unsigned*)Wsm[0][nr];
                const unsigned* ps = (const unsigned*)Wsm[1][nr];
                unsigned bb0 = pb[base + tig], bb1 = pb[base + tig + 4];
                unsigned bs0 = ps[base + tig], bs1 = ps[base + tig + 4];
#pragma unroll
                for (int mt = 0; mt < 2; mt++) {
                    mma16(acc[mt][nt], ab[mt], bb0, bb1);
                    mma16(acc[mt][nt], ab[mt], bs0, bs1);
                    mma16(acc[mt][nt], as_[mt], bb0, bb1);
                }
            }
        }
        __syncthreads();
    }
#pragma unroll
    for (int mt = 0; mt < 2; mt++)
#pragma unroll
        for (int nt = 0; nt < 4; nt++)
#pragma unroll
            for (int i = 0; i < 4; i++) {
                int gr = row0 + wm * 32 + mt * 16 + gid + 8 * (i >> 1);
                int gc = col0 + wn * 32 + nt * 8 + tig * 2 + (i & 1);
                if (gr < M && gc < G)
                    C[(long)gr * G + gc] = acc[mt][nt][i] + bias[gc];
            }
}

/* -------- fused GRU step via bf16 3-mma split --------------------------------
   h and Whh pre-split bf16 (stride KP, even, zero-padded). 64 rows x 48 cols
   (3 gates x 16 hc), 4 warps. Epilogue fuses gates and writes h fp32 + split,
   plus optional y split. ----------------------------------------------------- */
__global__ __launch_bounds__(128) void gru_step_mma(
    const float* __restrict__ hf_in, const bf* __restrict__ hb_in,
    const bf* __restrict__ hs_in,
    float* __restrict__ hf_out, bf* __restrict__ hb_out, bf* __restrict__ hs_out,
    const float* __restrict__ xw, const bf* __restrict__ Whh_b,
    const bf* __restrict__ Whh_s, const float* __restrict__ bhh,
    bf* __restrict__ y_b, bf* __restrict__ y_s,
    int H, int KP, int Nb, int T, int t_f, int t_b)
{
    __shared__ __align__(16) bf Hsm[2][64][20];
    __shared__ __align__(16) bf Wsm[2][48][20];
    int tid = threadIdx.x, lane = tid & 31, wid = tid >> 5;
    int gid = lane >> 2, tig = lane & 3;
    int r0 = blockIdx.x * 64;
    int dir = r0 / Nb;                 /* tiles never straddle dirs (Nb%64==0) */
    int n0 = r0 - dir * Nb;
    int h0 = blockIdx.y * 16;
    const bf* Wdb = Whh_b + (long)dir * 3 * H * KP;
    const bf* Wds = Whh_s + (long)dir * 3 * H * KP;
    const bf* hbd = hb_in + ((long)dir * Nb + n0) * KP;
    const bf* hsd = hs_in + ((long)dir * Nb + n0) * KP;

    float acc[6][4];
#pragma unroll
    for (int nt = 0; nt < 6; nt++)
#pragma unroll
        for (int i = 0; i < 4; i++) acc[nt][i] = 0.f;

    unsigned ph[2][4], pw[2][3];
    auto fetch = [&](int k0) {
#pragma unroll
        for (int j = 0; j < 4; j++) {
            int e = tid + j * 128, r = e >> 3, kk = e & 7;
            int gk = k0 + 2 * kk;
            bool v = (gk < KP);
            long off = (long)r * KP + gk;
            ph[0][j] = v ? *(const unsigned*)(hbd + off) : 0u;
            ph[1][j] = v ? *(const unsigned*)(hsd + off) : 0u;
        }
#pragma unroll
        for (int j = 0; j < 3; j++) {
            int e = tid + j * 128, r = e >> 3, kk = e & 7;
            int gate = r >> 4, hh = r & 15;
            int gk = k0 + 2 * kk;
            bool v = (gk < KP) && (h0 + hh < H);
            long off = ((long)gate * H + h0 + hh) * KP + gk;
            pw[0][j] = v ? *(const unsigned*)(Wdb + off) : 0u;
            pw[1][j] = v ? *(const unsigned*)(Wds + off) : 0u;
        }
    };
    fetch(0);
    for (int k0 = 0; k0 < KP; k0 += 16) {
#pragma unroll
        for (int j = 0; j < 4; j++) {
            int e = tid + j * 128, r = e >> 3, kk = e & 7;
            ((unsigned*)Hsm[0][r])[kk] = ph[0][j];
            ((unsigned*)Hsm[1][r])[kk] = ph[1][j];
        }
#pragma unroll
        for (int j = 0; j < 3; j++) {
            int e = tid + j * 128, r = e >> 3, kk = e & 7;
            ((unsigned*)Wsm[0][r])[kk] = pw[0][j];
            ((unsigned*)Wsm[1][r])[kk] = pw[1][j];
        }
        __syncthreads();
        if (k0 + 16 < KP) fetch(k0 + 16);
        int mr = wid * 16;
        unsigned ab[4], as_[4];
        {
            const unsigned* p0b = (const unsigned*)Hsm[0][mr + gid];
            const unsigned* p1b = (const unsigned*)Hsm[0][mr + gid + 8];
            const unsigned* p0s = (const unsigned*)Hsm[1][mr + gid];
            const unsigned* p1s = (const unsigned*)Hsm[1][mr + gid + 8];
            ab[0] = p0b[tig];     ab[1] = p1b[tig];
            ab[2] = p0b[tig + 4]; ab[3] = p1b[tig + 4];
            as_[0] = p0s[tig];     as_[1] = p1s[tig];
            as_[2] = p0s[tig + 4]; as_[3] = p1s[tig + 4];
        }
#pragma unroll
        for (int nt = 0; nt < 6; nt++) {
            const unsigned* pb = (const unsigned*)Wsm[0][nt * 8 + gid];
            const unsigned* ps = (const unsigned*)Wsm[1][nt * 8 + gid];
            unsigned bb0 = pb[tig], bb1 = pb[tig + 4];
            unsigned bs0 = ps[tig], bs1 = ps[tig + 4];
            mma16(acc[nt], ab, bb0, bb1);
            mma16(acc[nt], ab, bs0, bs1);
            mma16(acc[nt], as_, bb0, bb1);
        }
        __syncthreads();
    }

    int t = dir ? t_b : t_f;
#pragma unroll
    for (int nt = 0; nt < 2; nt++)
#pragma unroll
        for (int i = 0; i < 4; i++) {
            int n = n0 + wid * 16 + gid + 8 * (i >> 1);
            int hc = h0 + nt * 8 + tig * 2 + (i & 1);
            if (hc >= H) continue;
            float br = bhh[dir * 3 * H + hc];
            float bz = bhh[dir * 3 * H + H + hc];
            float bn = bhh[dir * 3 * H + 2 * H + hc];
            long xb = ((long)(dir * T + t) * Nb + n) * (3 * H);
            float xr = xw[xb + hc];
            float xz = xw[xb + H + hc];
            float xn = xw[xb + 2 * H + hc];
            float gr_ = acc[nt][i] + br;
            float gz_ = acc[nt + 2][i] + bz;
            float gn_ = acc[nt + 4][i] + bn;
            float rg = 1.f / (1.f + expf(-(xr + gr_)));
            float zg = 1.f / (1.f + expf(-(xz + gz_)));
            float ng = tanhf(xn + rg * gn_);
            long hidx = ((long)dir * Nb + n) * KP + hc;
            float hp = hf_in[hidx];
            float hn = (1.f - zg) * ng + zg * hp;
            hf_out[hidx] = hn;
            bf hb_, hs_; bsplit(hn, hb_, hs_);
            hb_out[hidx] = hb_;
            hs_out[hidx] = hs_;
            if (y_b) {
                long yi = ((long)t * Nb + n) * 2 * H + (long)dir * H + hc;
                y_b[yi] = hb_; y_s[yi] = hs_;
            }
        }
}

/* ---- concat [hf0|hb0|hf1|hb1] rows, split bf16 output ----------------------- */
__global__ void concat4_split(const float* __restrict__ h0f,
                              const float* __restrict__ h1f,
                              bf* __restrict__ ob, bf* __restrict__ os,
                              int Nrows, int H, int KP) {
    long idx = blockIdx.x * 256L + threadIdx.x;
    int C = 4 * H;
    if (idx >= (long)Nrows * C) return;
    int c = (int)(idx % C);
    long n = idx / C;
    float v;
    if (c < 2 * H) {
        int d = c / H, hh = c % H;
        v = h0f[((long)d * Nrows + n) * KP + hh];
    } else {
        int c2 = c - 2 * H;
        int d = c2 / H, hh = c2 % H;
        v = h1f[((long)d * Nrows + n) * KP + hh];
    }
    bf vb, vs; bsplit(v, vb, vs);
    ob[idx] = vb; os[idx] = vs;
}

/* ---- concat fp32 (final output) --------------------------------------------- */
__global__ void concat4_k(const float* __restrict__ h0f, const float* __restrict__ h1f,
                          float* __restrict__ out, int Nrows, int H, int KP) {
    long idx = blockIdx.x * 256L + threadIdx.x;
    int C = 4 * H;
    if (idx >= (long)Nrows * C) return;
    int c = (int)(idx % C);
    long n = idx / C;
    float v;
    if (c < 2 * H) {
        int d = c / H, hh = c % H;
        v = h0f[((long)d * Nrows + n) * KP + hh];
    } else {
        int c2 = c - 2 * H;
        int d = c2 / H, hh = c2 % H;
        v = h1f[((long)d * Nrows + n) * KP + hh];
    }
    out[idx] = v;
}

/* ---------------------------------- host ------------------------------------ */
extern "C" void kernel_launch(void* const* d_in, const int* in_sizes, int n_in,
                              void* d_out, int out_size) {
    const int*   x        = (const int*)  d_in[0];
    const float* emb      = (const float*)d_in[1];
    const float* we_Wih0  = (const float*)d_in[2];
    const float* we_Whh0  = (const float*)d_in[3];
    const float* we_bih0  = (const float*)d_in[4];
    const float* we_bhh0  = (const float*)d_in[5];
    const float* we_Wih1  = (const float*)d_in[6];
    const float* we_Whh1  = (const float*)d_in[7];
    const float* we_bih1  = (const float*)d_in[8];
    const float* we_bhh1  = (const float*)d_in[9];
    const float* se_Wih0  = (const float*)d_in[10];
    const float* se_Whh0  = (const float*)d_in[11];
    const float* se_bih0  = (const float*)d_in[12];
    const float* se_bhh0  = (const float*)d_in[13];
    const float* se_Wih1  = (const float*)d_in[14];
    const float* se_Whh1  = (const float*)d_in[15];
    const float* se_bih1  = (const float*)d_in[16];
    const float* se_bhh1  = (const float*)d_in[17];
    (void)in_sizes; (void)n_in; (void)out_size;

    bf *xe_b, *xe_s, *y0w_b, *y0w_s, *words_b, *words_s, *y0s_b, *y0s_s;
    float *xw, *hwf, *hsf;
    bf *hwb, *hws, *hsb, *hss;
    bf *wW0b,*wW0s,*wW1b,*wW1s,*wH0b,*wH0s,*wH1b,*wH1s;
    bf *sW0b,*sW0s,*sW1b,*sW1s,*sH0b,*sH0s,*sH1b,*sH1s;
    cudaGetSymbolAddress((void**)&xe_b, g_xe_b);   cudaGetSymbolAddress((void**)&xe_s, g_xe_s);
    cudaGetSymbolAddress((void**)&xw, g_xw);
    cudaGetSymbolAddress((void**)&y0w_b, g_y0w_b); cudaGetSymbolAddress((void**)&y0w_s, g_y0w_s);
    cudaGetSymbolAddress((void**)&words_b, g_words_b); cudaGetSymbolAddress((void**)&words_s, g_words_s);
    cudaGetSymbolAddress((void**)&y0s_b, g_y0s_b); cudaGetSymbolAddress((void**)&y0s_s, g_y0s_s);
    cudaGetSymbolAddress((void**)&hwf, g_hwf);     cudaGetSymbolAddress((void**)&hsf, g_hsf);
    cudaGetSymbolAddress((void**)&hwb, g_hwb);     cudaGetSymbolAddress((void**)&hws, g_hws);
    cudaGetSymbolAddress((void**)&hsb, g_hsb);     cudaGetSymbolAddress((void**)&hss, g_hss);
    cudaGetSymbolAddress((void**)&wW0b, g_weWih0_b); cudaGetSymbolAddress((void**)&wW0s, g_weWih0_s);
    cudaGetSymbolAddress((void**)&wW1b, g_weWih1_b); cudaGetSymbolAddress((void**)&wW1s, g_weWih1_s);
    cudaGetSymbolAddress((void**)&wH0b, g_weWhh0_b); cudaGetSymbolAddress((void**)&wH0s, g_weWhh0_s);
    cudaGetSymbolAddress((void**)&wH1b, g_weWhh1_b); cudaGetSymbolAddress((void**)&wH1s, g_weWhh1_s);
    cudaGetSymbolAddress((void**)&sW0b, g_seWih0_b); cudaGetSymbolAddress((void**)&sW0s, g_seWih0_s);
    cudaGetSymbolAddress((void**)&sW1b, g_seWih1_b); cudaGetSymbolAddress((void**)&sW1s, g_seWih1_s);
    cudaGetSymbolAddress((void**)&sH0b, g_seWhh0_b); cudaGetSymbolAddress((void**)&sH0s, g_seWhh0_s);
    cudaGetSymbolAddress((void**)&sH1b, g_seWhh1_b); cudaGetSymbolAddress((void**)&sH1s, g_seWhh1_s);

    float* hwF[4]; bf* hwB[4]; bf* hwS[4];
    float* hsF[4]; bf* hsB[4]; bf* hsS[4];
    for (int i = 0; i < 4; i++) {
        hwF[i] = hwf + (long)i * HWBUF_N; hwB[i] = hwb + (long)i * HWBUF_N; hwS[i] = hws + (long)i * HWBUF_N;
        hsF[i] = hsf + (long)i * HSBUF_N; hsB[i] = hsb + (long)i * HSBUF_N; hsS[i] = hss + (long)i * HSBUF_N;
    }

    auto SPLIT = [](const float* w, bf* b, bf* s, int rows, int K, int KP) {
        long n = (long)rows * KP;
        split_k<<<(unsigned)((n + 255) / 256), 256>>>(w, b, s, rows, K, KP);
    };

    /* 0. split weights */
    SPLIT(we_Wih0, wW0b, wW0s, 2*3*HW, E_DIM, E_DIM);
    SPLIT(we_Wih1, wW1b, wW1s, 2*3*HW, 2*HW,  2*HW);
    SPLIT(we_Whh0, wH0b, wH0s, 2*3*HW, HW,    HWP);
    SPLIT(we_Whh1, wH1b, wH1s, 2*3*HW, HW,    HWP);
    SPLIT(se_Wih0, sW0b, sW0s, 2*3*HS, 4*HW,  4*HW);
    SPLIT(se_Wih1, sW1b, sW1s, 2*3*HS, 2*HS,  2*HS);
    SPLIT(se_Whh0, sH0b, sH0s, 2*3*HS, HS,    HS);
    SPLIT(se_Whh1, sH1b, sH1s, 2*3*HS, HS,    HS);

    /* 1. embedding (split) */
    embed_split_k<<<(XE_N + 255) / 256, 256>>>(x, emb, xe_b, xe_s);

    /* 2. word layer0: xw precompute + 10 steps (ys -> y0w split) */
    for (int d = 0; d < 2; d++) {
        dim3 g((3 * HW + 63) / 64, (T_LEN * NW + 127) / 128);
        mma_gemm_bias<<<g, 256>>>(xe_b, xe_s,
                                  wW0b + (long)d * 3 * HW * E_DIM,
                                  wW0s + (long)d * 3 * HW * E_DIM,
                                  we_bih0 + d * 3 * HW,
                                  xw + (long)d * T_LEN * NW * 3 * HW,
                                  T_LEN * NW, 3 * HW, E_DIM);
    }
    cudaMemsetAsync(hwF[0], 0, sizeof(float) * HWBUF_N);
    cudaMemsetAsync(hwB[0], 0, sizeof(bf) * HWBUF_N);
    cudaMemsetAsync(hwS[0], 0, sizeof(bf) * HWBUF_N);
    {
        dim3 grid(2 * NW / 64, (HW + 15) / 16);
        for (int s = 0; s < T_LEN; s++) {
            int a = (s & 1), b = 1 - a;
            gru_step_mma<<<grid, 128>>>(hwF[a], hwB[a], hwS[a],
                                        hwF[b], hwB[b], hwS[b],
                                        xw, wH0b, wH0s, we_bhh0,
                                        y0w_b, y0w_s,
                                        HW, HWP, NW, T_LEN, s, T_LEN - 1 - s);
        }
    }
    /* final layer0 hidden in slot 0 (10 steps) */

    /* 3. word layer1: xw from y0w + 10 steps (no ys) */
    for (int d = 0; d < 2; d++) {
        dim3 g((3 * HW + 63) / 64, (T_LEN * NW + 127) / 128);
        mma_gemm_bias<<<g, 256>>>(y0w_b, y0w_s,
                                  wW1b + (long)d * 3 * HW * 2 * HW,
                                  wW1s + (long)d * 3 * HW * 2 * HW,
                                  we_bih1 + d * 3 * HW,
                                  xw + (long)d * T_LEN * NW * 3 * HW,
                                  T_LEN * NW, 3 * HW, 2 * HW);
    }
    cudaMemsetAsync(hwF[2], 0, sizeof(float) * HWBUF_N);
    cudaMemsetAsync(hwB[2], 0, sizeof(bf) * HWBUF_N);
    cudaMemsetAsync(hwS[2], 0, sizeof(bf) * HWBUF_N);
    {
        dim3 grid(2 * NW / 64, (HW + 15) / 16);
        for (int s = 0; s < T_LEN; s++) {
            int a = 2 + (s & 1), b = 2 + 1 - (s & 1);
            gru_step_mma<<<grid, 128>>>(hwF[a], hwB[a], hwS[a],
                                        hwF[b], hwB[b], hwS[b],
                                        xw, wH1b, wH1s, we_bhh1,
                                        (bf*)0, (bf*)0,
                                        HW, HWP, NW, T_LEN, s, T_LEN - 1 - s);
        }
    }

    /* 4. words = [hf0|hb0|hf1|hb1] split : [NW, 300] */
    concat4_split<<<(WORDS_N + 255) / 256, 256>>>(hwF[0], hwF[2],
                                                  words_b, words_s, NW, HW, HWP);

    /* 5. sentence layer0: xw precompute + 120 steps (ys -> y0s split) */
    for (int d = 0; d < 2; d++) {
        dim3 g((3 * HS + 63) / 64, (S_LEN * B_SZ + 127) / 128);
        mma_gemm_bias<<<g, 256>>>(words_b, words_s,
                                  sW0b + (long)d * 3 * HS * 4 * HW,
                                  sW0s + (long)d * 3 * HS * 4 * HW,
                                  se_bih0 + d * 3 * HS,
                                  xw + (long)d * S_LEN * B_SZ * 3 * HS,
                                  S_LEN * B_SZ, 3 * HS, 4 * HW);
    }
    cudaMemsetAsync(hsF[0], 0, sizeof(float) * HSBUF_N);
    cudaMemsetAsync(hsB[0], 0, sizeof(bf) * HSBUF_N);
    cudaMemsetAsync(hsS[0], 0, sizeof(bf) * HSBUF_N);
    {
        dim3 grid(2 * B_SZ / 64, (HS + 15) / 16);
        for (int s = 0; s < S_LEN; s++) {
            int a = (s & 1), b = 1 - a;
            gru_step_mma<<<grid, 128>>>(hsF[a], hsB[a], hsS[a],
                                        hsF[b], hsB[b], hsS[b],
                                        xw, sH0b, sH0s, se_bhh0,
                                        y0s_b, y0s_s,
                                        HS, HS, B_SZ, S_LEN, s, S_LEN - 1 - s);
        }
    }
    /* final in slot 0 (120 steps) */

    /* 6. sentence layer1: xw from y0s + 120 steps (no ys) */
    for (int d = 0; d < 2; d++) {
        dim3 g((3 * HS + 63) / 64, (S_LEN * B_SZ + 127) / 128);
        mma_gemm_bias<<<g, 256>>>(y0s_b, y0s_s,
                                  sW1b + (long)d * 3 * HS * 2 * HS,
                                  sW1s + (long)d * 3 * HS * 2 * HS,
                                  se_bih1 + d * 3 * HS,
                                  xw + (long)d * S_LEN * B_SZ * 3 * HS,
                                  S_LEN * B_SZ, 3 * HS, 2 * HS);
    }
    cudaMemsetAsync(hsF[2], 0, sizeof(float) * HSBUF_N);
    cudaMemsetAsync(hsB[2], 0, sizeof(bf) * HSBUF_N);
    cudaMemsetAsync(hsS[2], 0, sizeof(bf) * HSBUF_N);
    {
        dim3 grid(2 * B_SZ / 64, (HS + 15) / 16);
        for (int s = 0; s < S_LEN; s++) {
            int a = 2 + (s & 1), b = 2 + 1 - (s & 1);
            gru_step_mma<<<grid, 128>>>(hsF[a], hsB[a], hsS[a],
                                        hsF[b], hsB[b], hsS[b],
                                        xw, sH1b, sH1s, se_bhh1,
                                        (bf*)0, (bf*)0,
                                        HS, HS, B_SZ, S_LEN, s, S_LEN - 1 - s);
        }
    }

    /* 7. output [1, 128, 2800] = [sf0|sb0|sf1|sb1] per batch row */
    concat4_k<<<((long)B_SZ * 4 * HS + 255) / 256, 256>>>(hsF[0], hsF[2],
                                                          (float*)d_out,
                                                          B_SZ, HS, HS);
}

// round 8
// speedup vs baseline: 2.4167x; 1.4128x over previous
#include <cuda_runtime.h>
#include <cuda_bf16.h>
#include <math.h>

#define S_LEN 120
#define T_LEN 10
#define B_SZ  128
#define E_DIM 80
#define HW    75
#define HWP   76
#define HS    700
#define NW    (S_LEN * B_SZ)   /* 15360 word-level batch */

typedef __nv_bfloat16 bf;

#define XE_N    (T_LEN * NW * E_DIM)
#define XW_N    (2L * T_LEN * NW * (3 * HW))   /* 69.12M fp32; sentence reuse needs 64.51M */
#define Y0W_N   (T_LEN * NW * 2 * HW)
#define WORDS_N (NW * 4 * HW)
#define Y0S_N   ((long)S_LEN * B_SZ * 2 * HS)
#define HWBUF_N (2 * NW * HWP)
#define HSBUF_N (2 * B_SZ * HS)

#define NBLK_S  88            /* 2 dirs x 44 hc tiles, persistent sentence kernel */
#define WSTRW   356           /* u32 stride of W smem row (356 % 32 == 4 -> conflict-free) */
#define HSTRW   12            /* u32 stride of h staging row (12 % 32 == 12 -> conflict-free) */
#define SMEM_PERS ((2 * 48 * WSTRW + 2 * 2 * 128 * HSTRW) * 4)   /* 161280 B */

/* ---------------- persistent scratch (device globals; no allocs) ------------- */
__device__ bf    g_xe_b[XE_N];
__device__ float g_xw[XW_N];
__device__ bf    g_y0w_b[Y0W_N];
__device__ bf    g_words_b[WORDS_N];
__device__ bf    g_y0s_b[Y0S_N];
__device__ float g_hwf[4][HWBUF_N];
__device__ bf    g_hwb[4][HWBUF_N], g_hws[4][HWBUF_N];
__device__ float g_hsf[4][HSBUF_N];
__device__ bf    g_hsb[4][HSBUF_N], g_hss[4][HSBUF_N];
__device__ unsigned g_bar;
/* weight splits */
__device__ bf g_weWih0_b[2*3*HW*E_DIM],  g_weWih0_s[2*3*HW*E_DIM];
__device__ bf g_weWih1_b[2*3*HW*2*HW],   g_weWih1_s[2*3*HW*2*HW];
__device__ bf g_weWhh0_b[2*3*HW*HWP],    g_weWhh0_s[2*3*HW*HWP];
__device__ bf g_weWhh1_b[2*3*HW*HWP],    g_weWhh1_s[2*3*HW*HWP];
__device__ bf g_seWih0_b[2*3*HS*4*HW],   g_seWih0_s[2*3*HS*4*HW];
__device__ bf g_seWih1_b[2*3*HS*2*HS],   g_seWih1_s[2*3*HS*2*HS];
__device__ bf g_seWhh0_b[2*3*HS*HS],     g_seWhh0_s[2*3*HS*HS];
__device__ bf g_seWhh1_b[2*3*HS*HS],     g_seWhh1_s[2*3*HS*HS];

/* ---------------- helpers ---------------------------------------------------- */
__device__ __forceinline__ void bsplit(float v, bf &b, bf &s) {
    b = __float2bfloat16_rn(v);
    s = __float2bfloat16_rn(v - __bfloat162float(b));
}
__device__ __forceinline__ void mma16(float d[4], const unsigned a[4],
                                      unsigned b0, unsigned b1) {
    asm volatile(
        "mma.sync.aligned.m16n8k16.row.col.f32.bf16.bf16.f32 "
        "{%0,%1,%2,%3},{%4,%5,%6,%7},{%8,%9},{%0,%1,%2,%3};"
        : "+f"(d[0]), "+f"(d[1]), "+f"(d[2]), "+f"(d[3])
        : "r"(a[0]), "r"(a[1]), "r"(a[2]), "r"(a[3]), "r"(b0), "r"(b1));
}

/* ---------------- weight split: fp32 [rows,K] -> bf16 big/small [rows,KP] ---- */
__global__ void split_k(const float* __restrict__ W, bf* __restrict__ b,
                        bf* __restrict__ s, int rows, int K, int KP) {
    long idx = blockIdx.x * 256L + threadIdx.x;
    if (idx >= (long)rows * KP) return;
    int k = (int)(idx % KP);
    long r = idx / KP;
    float v = (k < K) ? W[r * K + k] : 0.f;
    bf vb, vs; bsplit(v, vb, vs);
    b[idx] = vb; s[idx] = vs;
}

/* ---------------- embedding gather (single bf16) ------------------------------ */
__global__ void embed_k(const int* __restrict__ x, const float* __restrict__ emb,
                        bf* __restrict__ xb) {
    long idx = blockIdx.x * 256L + threadIdx.x;
    if (idx >= XE_N) return;
    int e = (int)(idx % E_DIM);
    int n = (int)((idx / E_DIM) % NW);
    int t = (int)(idx / ((long)E_DIM * NW));
    int s = n >> 7, bb_ = n & 127;
    int tok = x[(s * T_LEN + t) * B_SZ + bb_];
    xb[idx] = __float2bfloat16_rn(emb[(long)tok * E_DIM + e]);
}

/* -------- C[m][g] = bias[g] + A[m,:]·W[g,:]  (A single bf16, W split, 2 mma) -- */
__global__ __launch_bounds__(256) void mma_gemm_bias(
    const bf* __restrict__ Ag, const bf* __restrict__ Wg_b,
    const bf* __restrict__ Wg_s, const float* __restrict__ bias,
    float* __restrict__ C, int M, int G, int K)
{
    __shared__ __align__(16) bf Asm[128][36];
    __shared__ __align__(16) bf Wsm[2][64][36];
    int tid = threadIdx.x, lane = tid & 31, wid = tid >> 5;
    int gid = lane >> 2, tig = lane & 3;
    int wm = wid & 3, wn = wid >> 2;
    int row0 = blockIdx.y * 128, col0 = blockIdx.x * 64;

    float acc[2][4][4];
#pragma unroll
    for (int mt = 0; mt < 2; mt++)
#pragma unroll
        for (int nt = 0; nt < 4; nt++)
#pragma unroll
            for (int i = 0; i < 4; i++) acc[mt][nt][i] = 0.f;

    unsigned pa[8], pw[8];
    auto fetch = [&](int k0) {
#pragma unroll
        for (int j = 0; j < 8; j++) {
            int e = tid + j * 256, r = e >> 4, kk = e & 15;
            int gk = k0 + 2 * kk, gr = row0 + r;
            pa[j] = ((gk < K) && (gr < M)) ? *(const unsigned*)(Ag + (long)gr * K + gk) : 0u;
        }
#pragma unroll
        for (int j = 0; j < 8; j++) {
            int e = tid + j * 256, arr = e >> 10, rem = e & 1023;
            int r = rem >> 4, kk = rem & 15;
            int gk = k0 + 2 * kk, gc = col0 + r;
            const bf* src = arr ? Wg_s : Wg_b;
            pw[j] = ((gk < K) && (gc < G)) ? *(const unsigned*)(src + (long)gc * K + gk) : 0u;
        }
    };
    fetch(0);
    for (int k0 = 0; k0 < K; k0 += 32) {
#pragma unroll
        for (int j = 0; j < 8; j++) {
            int e = tid + j * 256, r = e >> 4, kk = e & 15;
            ((unsigned*)Asm[r])[kk] = pa[j];
        }
#pragma unroll
        for (int j = 0; j < 8; j++) {
            int e = tid + j * 256, arr = e >> 10, rem = e & 1023;
            int r = rem >> 4, kk = rem & 15;
            ((unsigned*)Wsm[arr][r])[kk] = pw[j];
        }
        __syncthreads();
        if (k0 + 32 < K) fetch(k0 + 32);
#pragma unroll
        for (int half = 0; half < 2; half++) {
            int base = half * 8;
            unsigned ab[2][4];
#pragma unroll
            for (int mt = 0; mt < 2; mt++) {
                int mr = wm * 32 + mt * 16;
                const unsigned* p0 = (const unsigned*)Asm[mr + gid];
                const unsigned* p1 = (const unsigned*)Asm[mr + gid + 8];
                ab[mt][0] = p0[base + tig];     ab[mt][1] = p1[base + tig];
                ab[mt][2] = p0[base + tig + 4]; ab[mt][3] = p1[base + tig + 4];
            }
#pragma unroll
            for (int nt = 0; nt < 4; nt++) {
                int nr = wn * 32 + nt * 8 + gid;
                const unsigned* pb = (const unsigned*)Wsm[0][nr];
                const unsigned* ps = (const unsigned*)Wsm[1][nr];
                unsigned bb0 = pb[base + tig], bb1 = pb[base + tig + 4];
                unsigned bs0 = ps[base + tig], bs1 = ps[base + tig + 4];
#pragma unroll
                for (int mt = 0; mt < 2; mt++) {
                    mma16(acc[mt][nt], ab[mt], bb0, bb1);
                    mma16(acc[mt][nt], ab[mt], bs0, bs1);
                }
            }
        }
        __syncthreads();
    }
#pragma unroll
    for (int mt = 0; mt < 2; mt++)
#pragma unroll
        for (int nt = 0; nt < 4; nt++)
#pragma unroll
            for (int i = 0; i < 4; i++) {
                int gr = row0 + wm * 32 + mt * 16 + gid + 8 * (i >> 1);
                int gc = col0 + wn * 32 + nt * 8 + tig * 2 + (i & 1);
                if (gr < M && gc < G)
                    C[(long)gr * G + gc] = acc[mt][nt][i] + bias[gc];
            }
}

/* -------- word GRU step (3-mma split, per-step launch) ----------------------- */
__global__ __launch_bounds__(128) void gru_step_mma(
    const float* __restrict__ hf_in, const bf* __restrict__ hb_in,
    const bf* __restrict__ hs_in,
    float* __restrict__ hf_out, bf* __restrict__ hb_out, bf* __restrict__ hs_out,
    const float* __restrict__ xw, const bf* __restrict__ Whh_b,
    const bf* __restrict__ Whh_s, const float* __restrict__ bhh,
    bf* __restrict__ y_b,
    int H, int KP, int Nb, int T, int t_f, int t_b)
{
    __shared__ __align__(16) bf Hsm[2][64][20];
    __shared__ __align__(16) bf Wsm[2][48][20];
    int tid = threadIdx.x, lane = tid & 31, wid = tid >> 5;
    int gid = lane >> 2, tig = lane & 3;
    int r0 = blockIdx.x * 64;
    int dir = r0 / Nb;
    int n0 = r0 - dir * Nb;
    int h0 = blockIdx.y * 16;
    const bf* Wdb = Whh_b + (long)dir * 3 * H * KP;
    const bf* Wds = Whh_s + (long)dir * 3 * H * KP;
    const bf* hbd = hb_in + ((long)dir * Nb + n0) * KP;
    const bf* hsd = hs_in + ((long)dir * Nb + n0) * KP;

    float acc[6][4];
#pragma unroll
    for (int nt = 0; nt < 6; nt++)
#pragma unroll
        for (int i = 0; i < 4; i++) acc[nt][i] = 0.f;

    unsigned ph[2][4], pw[2][3];
    auto fetch = [&](int k0) {
#pragma unroll
        for (int j = 0; j < 4; j++) {
            int e = tid + j * 128, r = e >> 3, kk = e & 7;
            int gk = k0 + 2 * kk;
            bool v = (gk < KP);
            long off = (long)r * KP + gk;
            ph[0][j] = v ? *(const unsigned*)(hbd + off) : 0u;
            ph[1][j] = v ? *(const unsigned*)(hsd + off) : 0u;
        }
#pragma unroll
        for (int j = 0; j < 3; j++) {
            int e = tid + j * 128, r = e >> 3, kk = e & 7;
            int gate = r >> 4, hh = r & 15;
            int gk = k0 + 2 * kk;
            bool v = (gk < KP) && (h0 + hh < H);
            long off = ((long)gate * H + h0 + hh) * KP + gk;
            pw[0][j] = v ? *(const unsigned*)(Wdb + off) : 0u;
            pw[1][j] = v ? *(const unsigned*)(Wds + off) : 0u;
        }
    };
    fetch(0);
    for (int k0 = 0; k0 < KP; k0 += 16) {
#pragma unroll
        for (int j = 0; j < 4; j++) {
            int e = tid + j * 128, r = e >> 3, kk = e & 7;
            ((unsigned*)Hsm[0][r])[kk] = ph[0][j];
            ((unsigned*)Hsm[1][r])[kk] = ph[1][j];
        }
#pragma unroll
        for (int j = 0; j < 3; j++) {
            int e = tid + j * 128, r = e >> 3, kk = e & 7;
            ((unsigned*)Wsm[0][r])[kk] = pw[0][j];
            ((unsigned*)Wsm[1][r])[kk] = pw[1][j];
        }
        __syncthreads();
        if (k0 + 16 < KP) fetch(k0 + 16);
        int mr = wid * 16;
        unsigned ab[4], as_[4];
        {
            const unsigned* p0b = (const unsigned*)Hsm[0][mr + gid];
            const unsigned* p1b = (const unsigned*)Hsm[0][mr + gid + 8];
            const unsigned* p0s = (const unsigned*)Hsm[1][mr + gid];
            const unsigned* p1s = (const unsigned*)Hsm[1][mr + gid + 8];
            ab[0] = p0b[tig];      ab[1] = p1b[tig];
            ab[2] = p0b[tig + 4];  ab[3] = p1b[tig + 4];
            as_[0] = p0s[tig];     as_[1] = p1s[tig];
            as_[2] = p0s[tig + 4]; as_[3] = p1s[tig + 4];
        }
#pragma unroll
        for (int nt = 0; nt < 6; nt++) {
            const unsigned* pb = (const unsigned*)Wsm[0][nt * 8 + gid];
            const unsigned* ps = (const unsigned*)Wsm[1][nt * 8 + gid];
            unsigned bb0 = pb[tig], bb1 = pb[tig + 4];
            unsigned bs0 = ps[tig], bs1 = ps[tig + 4];
            mma16(acc[nt], ab, bb0, bb1);
            mma16(acc[nt], ab, bs0, bs1);
            mma16(acc[nt], as_, bb0, bb1);
        }
        __syncthreads();
    }

    int t = dir ? t_b : t_f;
#pragma unroll
    for (int nt = 0; nt < 2; nt++)
#pragma unroll
        for (int i = 0; i < 4; i++) {
            int n = n0 + wid * 16 + gid + 8 * (i >> 1);
            int hc = h0 + nt * 8 + tig * 2 + (i & 1);
            if (hc >= H) continue;
            float br = bhh[dir * 3 * H + hc];
            float bz = bhh[dir * 3 * H + H + hc];
            float bn = bhh[dir * 3 * H + 2 * H + hc];
            long xb = ((long)(dir * T + t) * Nb + n) * (3 * H);
            float xr = xw[xb + hc];
            float xz = xw[xb + H + hc];
            float xn = xw[xb + 2 * H + hc];
            float gr_ = acc[nt][i] + br;
            float gz_ = acc[nt + 2][i] + bz;
            float gn_ = acc[nt + 4][i] + bn;
            float rg = 1.f / (1.f + expf(-(xr + gr_)));
            float zg = 1.f / (1.f + expf(-(xz + gz_)));
            float ng = tanhf(xn + rg * gn_);
            long hidx = ((long)dir * Nb + n) * KP + hc;
            float hp = hf_in[hidx];
            float hn = (1.f - zg) * ng + zg * hp;
            hf_out[hidx] = hn;
            bf hb_, hs_; bsplit(hn, hb_, hs_);
            hb_out[hidx] = hb_;
            hs_out[hidx] = hs_;
            if (y_b)
                y_b[((long)t * Nb + n) * 2 * H + (long)dir * H + hc] = hb_;
        }
}

/* -------- persistent sentence GRU: all 120 steps, W slice cached in SMEM -----
   Grid = 88 blocks (2 dirs x 44 hc-tiles), 256 threads (8 warps, one 16-row
   m-tile each over all 128 rows of the dir). Manual grid barrier per step
   (88 <= 148 SMs, 1 block/SM -> all co-resident in wave 1). ----------------- */
__global__ __launch_bounds__(256) void gru_sent_persistent(
    const bf* __restrict__ Whh_b, const bf* __restrict__ Whh_s,
    const float* __restrict__ bhh, const float* __restrict__ xw,
    float* __restrict__ hfA, bf* __restrict__ hbA, bf* __restrict__ hsA,
    float* __restrict__ hfB, bf* __restrict__ hbB, bf* __restrict__ hsB,
    bf* __restrict__ y_b, unsigned* __restrict__ bar)
{
    extern __shared__ __align__(16) unsigned smem_u[];
    unsigned* Wu   = smem_u;                        /* [2][48][WSTRW] */
    unsigned* Hst  = smem_u + 2 * 48 * WSTRW;       /* [2buf][2arr][128][HSTRW] */

    int tid = threadIdx.x, lane = tid & 31, wid = tid >> 5;
    int gid = lane >> 2, tig = lane & 3;
    int dir = blockIdx.x / 44;
    int h0 = (blockIdx.x % 44) * 16;

    /* ---- load this block's Whh slice (3 gates x 16 hc x 700) once ---------- */
    for (int e = tid; e < 2 * 48 * 352; e += 256) {
        int arr = e / (48 * 352);
        int rem = e % (48 * 352);
        int r = rem / 352, w = rem % 352;
        int gate = r >> 4, hc = h0 + (r & 15);
        unsigned v = 0;
        if (w < 350 && hc < HS) {
            const bf* src = (arr ? Whh_s : Whh_b) +
                            (((long)dir * 3 + gate) * HS + hc) * (long)HS + 2 * w;
            v = *(const unsigned*)src;
        }
        Wu[(long)arr * 48 * WSTRW + r * WSTRW + w] = v;
    }
    __syncthreads();

    unsigned ph[8];
    for (int s = 0; s < S_LEN; s++) {
        const float* hf_in = (s & 1) ? hfB : hfA;
        const bf*    hb_in = (s & 1) ? hbB : hbA;
        const bf*    hs_in = (s & 1) ? hsB : hsA;
        float* hf_out = (s & 1) ? hfA : hfB;
        bf*    hb_out = (s & 1) ? hbA : hbB;
        bf*    hs_out = (s & 1) ? hsA : hsB;

        float acc[6][4];
#pragma unroll
        for (int nt = 0; nt < 6; nt++)
#pragma unroll
            for (int i = 0; i < 4; i++) acc[nt][i] = 0.f;

        /* fetch iter 0 */
#pragma unroll
        for (int j = 0; j < 8; j++) {
            int e = tid + j * 256, arr = e >> 10, rem = e & 1023;
            int row = rem >> 3, w = rem & 7;
            const bf* hp = arr ? hs_in : hb_in;
            ph[j] = (w < 350) ? *(const unsigned*)(hp + ((long)dir * 128 + row) * HS + 2 * w)
                              : 0u;
        }
        for (int it = 0; it < 44; it++) {
            int buf = it & 1;
#pragma unroll
            for (int j = 0; j < 8; j++) {
                int e = tid + j * 256, arr = e >> 10, rem = e & 1023;
                int row = rem >> 3, w = rem & 7;
                Hst[((buf * 2 + arr) * 128 + row) * HSTRW + w] = ph[j];
            }
            if (it + 1 < 44) {
                int g0 = (it + 1) * 8;
#pragma unroll
                for (int j = 0; j < 8; j++) {
                    int e = tid + j * 256, arr = e >> 10, rem = e & 1023;
                    int row = rem >> 3, w = rem & 7;
                    int g = g0 + w;
                    const bf* hp = arr ? hs_in : hb_in;
                    ph[j] = (g < 350) ? *(const unsigned*)(hp + ((long)dir * 128 + row) * HS + 2 * g)
                                      : 0u;
                }
            }
            __syncthreads();
            int mrow = wid * 16;
            unsigned ab[4], as_[4];
            {
                const unsigned* p0b = Hst + ((buf * 2 + 0) * 128 + mrow + gid) * HSTRW;
                const unsigned* p1b = Hst + ((buf * 2 + 0) * 128 + mrow + gid + 8) * HSTRW;
                const unsigned* p0s = Hst + ((buf * 2 + 1) * 128 + mrow + gid) * HSTRW;
                const unsigned* p1s = Hst + ((buf * 2 + 1) * 128 + mrow + gid + 8) * HSTRW;
                ab[0] = p0b[tig];      ab[1] = p1b[tig];
                ab[2] = p0b[tig + 4];  ab[3] = p1b[tig + 4];
                as_[0] = p0s[tig];     as_[1] = p1s[tig];
                as_[2] = p0s[tig + 4]; as_[3] = p1s[tig + 4];
            }
            int kb = it * 8;
#pragma unroll
            for (int nt = 0; nt < 6; nt++) {
                const unsigned* pb = Wu + (nt * 8 + gid) * WSTRW + kb;
                const unsigned* ps = Wu + (long)48 * WSTRW + (nt * 8 + gid) * WSTRW + kb;
                unsigned bb0 = pb[tig], bb1 = pb[tig + 4];
                unsigned bs0 = ps[tig], bs1 = ps[tig + 4];
                mma16(acc[nt], ab, bb0, bb1);
                mma16(acc[nt], ab, bs0, bs1);
                mma16(acc[nt], as_, bb0, bb1);
            }
        }

        /* epilogue: gates + h update */
        int t = dir ? (S_LEN - 1 - s) : s;
#pragma unroll
        for (int nt = 0; nt < 2; nt++)
#pragma unroll
            for (int i = 0; i < 4; i++) {
                int n = wid * 16 + gid + 8 * (i >> 1);
                int hc = h0 + nt * 8 + tig * 2 + (i & 1);
                if (hc >= HS) continue;
                float br = bhh[dir * 3 * HS + hc];
                float bz = bhh[dir * 3 * HS + HS + hc];
                float bn = bhh[dir * 3 * HS + 2 * HS + hc];
                long xb = ((long)(dir * S_LEN + t) * 128 + n) * (3 * HS);
                float xr = xw[xb + hc];
                float xz = xw[xb + HS + hc];
                float xn = xw[xb + 2 * HS + hc];
                float gr_ = acc[nt][i] + br;
                float gz_ = acc[nt + 2][i] + bz;
                float gn_ = acc[nt + 4][i] + bn;
                float rg = 1.f / (1.f + expf(-(xr + gr_)));
                float zg = 1.f / (1.f + expf(-(xz + gz_)));
                float ng = tanhf(xn + rg * gn_);
                long hidx = ((long)dir * 128 + n) * HS + hc;
                float hp = hf_in[hidx];
                float hn = (1.f - zg) * ng + zg * hp;
                hf_out[hidx] = hn;
                bf hb_, hs_; bsplit(hn, hb_, hs_);
                hb_out[hidx] = hb_;
                hs_out[hidx] = hs_;
                if (y_b)
                    y_b[((long)t * 128 + n) * 2 * HS + (long)dir * HS + hc] = hb_;
            }

        /* grid barrier */
        __syncthreads();
        if (tid == 0) {
            __threadfence();
            atomicAdd(bar, 1u);
            unsigned target = (unsigned)NBLK_S * (s + 1);
            while (atomicAdd(bar, 0u) < target) __nanosleep(32);
            __threadfence();
        }
        __syncthreads();
    }
}

/* ---- concat [hf0|hb0|hf1|hb1] rows, single bf16 output ---------------------- */
__global__ void concat4_single(const float* __restrict__ h0f,
                               const float* __restrict__ h1f,
                               bf* __restrict__ ob, int Nrows, int H, int KP) {
    long idx = blockIdx.x * 256L + threadIdx.x;
    int C = 4 * H;
    if (idx >= (long)Nrows * C) return;
    int c = (int)(idx % C);
    long n = idx / C;
    float v;
    if (c < 2 * H) {
        int d = c / H, hh = c % H;
        v = h0f[((long)d * Nrows + n) * KP + hh];
    } else {
        int c2 = c - 2 * H;
        int d = c2 / H, hh = c2 % H;
        v = h1f[((long)d * Nrows + n) * KP + hh];
    }
    ob[idx] = __float2bfloat16_rn(v);
}

/* ---- concat fp32 (final output) --------------------------------------------- */
__global__ void concat4_k(const float* __restrict__ h0f, const float* __restrict__ h1f,
                          float* __restrict__ out, int Nrows, int H, int KP) {
    long idx = blockIdx.x * 256L + threadIdx.x;
    int C = 4 * H;
    if (idx >= (long)Nrows * C) return;
    int c = (int)(idx % C);
    long n = idx / C;
    float v;
    if (c < 2 * H) {
        int d = c / H, hh = c % H;
        v = h0f[((long)d * Nrows + n) * KP + hh];
    } else {
        int c2 = c - 2 * H;
        int d = c2 / H, hh = c2 % H;
        v = h1f[((long)d * Nrows + n) * KP + hh];
    }
    out[idx] = v;
}

/* ---------------------------------- host ------------------------------------ */
extern "C" void kernel_launch(void* const* d_in, const int* in_sizes, int n_in,
                              void* d_out, int out_size) {
    const int*   x        = (const int*)  d_in[0];
    const float* emb      = (const float*)d_in[1];
    const float* we_Wih0  = (const float*)d_in[2];
    const float* we_Whh0  = (const float*)d_in[3];
    const float* we_bih0  = (const float*)d_in[4];
    const float* we_bhh0  = (const float*)d_in[5];
    const float* we_Wih1  = (const float*)d_in[6];
    const float* we_Whh1  = (const float*)d_in[7];
    const float* we_bih1  = (const float*)d_in[8];
    const float* we_bhh1  = (const float*)d_in[9];
    const float* se_Wih0  = (const float*)d_in[10];
    const float* se_Whh0  = (const float*)d_in[11];
    const float* se_bih0  = (const float*)d_in[12];
    const float* se_bhh0  = (const float*)d_in[13];
    const float* se_Wih1  = (const float*)d_in[14];
    const float* se_Whh1  = (const float*)d_in[15];
    const float* se_bih1  = (const float*)d_in[16];
    const float* se_bhh1  = (const float*)d_in[17];
    (void)in_sizes; (void)n_in; (void)out_size;

    bf *xe_b, *y0w_b, *words_b, *y0s_b;
    float *xw, *hwf, *hsf;
    bf *hwb, *hws, *hsb, *hss;
    unsigned* bar;
    bf *wW0b,*wW0s,*wW1b,*wW1s,*wH0b,*wH0s,*wH1b,*wH1s;
    bf *sW0b,*sW0s,*sW1b,*sW1s,*sH0b,*sH0s,*sH1b,*sH1s;
    cudaGetSymbolAddress((void**)&xe_b, g_xe_b);
    cudaGetSymbolAddress((void**)&xw, g_xw);
    cudaGetSymbolAddress((void**)&y0w_b, g_y0w_b);
    cudaGetSymbolAddress((void**)&words_b, g_words_b);
    cudaGetSymbolAddress((void**)&y0s_b, g_y0s_b);
    cudaGetSymbolAddress((void**)&hwf, g_hwf);     cudaGetSymbolAddress((void**)&hsf, g_hsf);
    cudaGetSymbolAddress((void**)&hwb, g_hwb);     cudaGetSymbolAddress((void**)&hws, g_hws);
    cudaGetSymbolAddress((void**)&hsb, g_hsb);     cudaGetSymbolAddress((void**)&hss, g_hss);
    cudaGetSymbolAddress((void**)&bar, g_bar);
    cudaGetSymbolAddress((void**)&wW0b, g_weWih0_b); cudaGetSymbolAddress((void**)&wW0s, g_weWih0_s);
    cudaGetSymbolAddress((void**)&wW1b, g_weWih1_b); cudaGetSymbolAddress((void**)&wW1s, g_weWih1_s);
    cudaGetSymbolAddress((void**)&wH0b, g_weWhh0_b); cudaGetSymbolAddress((void**)&wH0s, g_weWhh0_s);
    cudaGetSymbolAddress((void**)&wH1b, g_weWhh1_b); cudaGetSymbolAddress((void**)&wH1s, g_weWhh1_s);
    cudaGetSymbolAddress((void**)&sW0b, g_seWih0_b); cudaGetSymbolAddress((void**)&sW0s, g_seWih0_s);
    cudaGetSymbolAddress((void**)&sW1b, g_seWih1_b); cudaGetSymbolAddress((void**)&sW1s, g_seWih1_s);
    cudaGetSymbolAddress((void**)&sH0b, g_seWhh0_b); cudaGetSymbolAddress((void**)&sH0s, g_seWhh0_s);
    cudaGetSymbolAddress((void**)&sH1b, g_seWhh1_b); cudaGetSymbolAddress((void**)&sH1s, g_seWhh1_s);

    cudaFuncSetAttribute(gru_sent_persistent,
                         cudaFuncAttributeMaxDynamicSharedMemorySize, SMEM_PERS);

    float* hwF[4]; bf* hwB[4]; bf* hwS[4];
    float* hsF[4]; bf* hsB[4]; bf* hsS[4];
    for (int i = 0; i < 4; i++) {
        hwF[i] = hwf + (long)i * HWBUF_N; hwB[i] = hwb + (long)i * HWBUF_N; hwS[i] = hws + (long)i * HWBUF_N;
        hsF[i] = hsf + (long)i * HSBUF_N; hsB[i] = hsb + (long)i * HSBUF_N; hsS[i] = hss + (long)i * HSBUF_N;
    }

    auto SPLIT = [](const float* w, bf* b, bf* s, int rows, int K, int KP) {
        long n = (long)rows * KP;
        split_k<<<(unsigned)((n + 255) / 256), 256>>>(w, b, s, rows, K, KP);
    };

    /* 0. split weights */
    SPLIT(we_Wih0, wW0b, wW0s, 2*3*HW, E_DIM, E_DIM);
    SPLIT(we_Wih1, wW1b, wW1s, 2*3*HW, 2*HW,  2*HW);
    SPLIT(we_Whh0, wH0b, wH0s, 2*3*HW, HW,    HWP);
    SPLIT(we_Whh1, wH1b, wH1s, 2*3*HW, HW,    HWP);
    SPLIT(se_Wih0, sW0b, sW0s, 2*3*HS, 4*HW,  4*HW);
    SPLIT(se_Wih1, sW1b, sW1s, 2*3*HS, 2*HS,  2*HS);
    SPLIT(se_Whh0, sH0b, sH0s, 2*3*HS, HS,    HS);
    SPLIT(se_Whh1, sH1b, sH1s, 2*3*HS, HS,    HS);

    /* 1. embedding */
    embed_k<<<(XE_N + 255) / 256, 256>>>(x, emb, xe_b);

    /* 2. word layer0: xw precompute + 10 steps (ys -> y0w) */
    for (int d = 0; d < 2; d++) {
        dim3 g((3 * HW + 63) / 64, (T_LEN * NW + 127) / 128);
        mma_gemm_bias<<<g, 256>>>(xe_b,
                                  wW0b + (long)d * 3 * HW * E_DIM,
                                  wW0s + (long)d * 3 * HW * E_DIM,
                                  we_bih0 + d * 3 * HW,
                                  xw + (long)d * T_LEN * NW * 3 * HW,
                                  T_LEN * NW, 3 * HW, E_DIM);
    }
    cudaMemsetAsync(hwF[0], 0, sizeof(float) * HWBUF_N);
    cudaMemsetAsync(hwB[0], 0, sizeof(bf) * HWBUF_N);
    cudaMemsetAsync(hwS[0], 0, sizeof(bf) * HWBUF_N);
    {
        dim3 grid(2 * NW / 64, (HW + 15) / 16);
        for (int s = 0; s < T_LEN; s++) {
            int a = (s & 1), b = 1 - a;
            gru_step_mma<<<grid, 128>>>(hwF[a], hwB[a], hwS[a],
                                        hwF[b], hwB[b], hwS[b],
                                        xw, wH0b, wH0s, we_bhh0, y0w_b,
                                        HW, HWP, NW, T_LEN, s, T_LEN - 1 - s);
        }
    }

    /* 3. word layer1: xw from y0w + 10 steps (no ys) */
    for (int d = 0; d < 2; d++) {
        dim3 g((3 * HW + 63) / 64, (T_LEN * NW + 127) / 128);
        mma_gemm_bias<<<g, 256>>>(y0w_b,
                                  wW1b + (long)d * 3 * HW * 2 * HW,
                                  wW1s + (long)d * 3 * HW * 2 * HW,
                                  we_bih1 + d * 3 * HW,
                                  xw + (long)d * T_LEN * NW * 3 * HW,
                                  T_LEN * NW, 3 * HW, 2 * HW);
    }
    cudaMemsetAsync(hwF[2], 0, sizeof(float) * HWBUF_N);
    cudaMemsetAsync(hwB[2], 0, sizeof(bf) * HWBUF_N);
    cudaMemsetAsync(hwS[2], 0, sizeof(bf) * HWBUF_N);
    {
        dim3 grid(2 * NW / 64, (HW + 15) / 16);
        for (int s = 0; s < T_LEN; s++) {
            int a = 2 + (s & 1), b = 2 + 1 - (s & 1);
            gru_step_mma<<<grid, 128>>>(hwF[a], hwB[a], hwS[a],
                                        hwF[b], hwB[b], hwS[b],
                                        xw, wH1b, wH1s, we_bhh1, (bf*)0,
                                        HW, HWP, NW, T_LEN, s, T_LEN - 1 - s);
        }
    }

    /* 4. words = [hf0|hb0|hf1|hb1] : [NW, 300] bf16 */
    concat4_single<<<(WORDS_N + 255) / 256, 256>>>(hwF[0], hwF[2],
                                                   words_b, NW, HW, HWP);

    /* 5. sentence layer0: xw precompute + persistent 120-step recurrence */
    for (int d = 0; d < 2; d++) {
        dim3 g((3 * HS + 63) / 64, (S_LEN * B_SZ + 127) / 128);
        mma_gemm_bias<<<g, 256>>>(words_b,
                                  sW0b + (long)d * 3 * HS * 4 * HW,
                                  sW0s + (long)d * 3 * HS * 4 * HW,
                                  se_bih0 + d * 3 * HS,
                                  xw + (long)d * S_LEN * B_SZ * 3 * HS,
                                  S_LEN * B_SZ, 3 * HS, 4 * HW);
    }
    cudaMemsetAsync(hsF[0], 0, sizeof(float) * HSBUF_N);
    cudaMemsetAsync(hsB[0], 0, sizeof(bf) * HSBUF_N);
    cudaMemsetAsync(hsS[0], 0, sizeof(bf) * HSBUF_N);
    cudaMemsetAsync(bar, 0, sizeof(unsigned));
    gru_sent_persistent<<<NBLK_S, 256, SMEM_PERS>>>(
        sH0b, sH0s, se_bhh0, xw,
        hsF[0], hsB[0], hsS[0], hsF[1], hsB[1], hsS[1],
        y0s_b, bar);
    /* final (120 steps, even) in slot 0 */

    /* 6. sentence layer1: xw from y0s + persistent 120 steps (no ys) */
    for (int d = 0; d < 2; d++) {
        dim3 g((3 * HS + 63) / 64, (S_LEN * B_SZ + 127) / 128);
        mma_gemm_bias<<<g, 256>>>(y0s_b,
                                  sW1b + (long)d * 3 * HS * 2 * HS,
                                  sW1s + (long)d * 3 * HS * 2 * HS,
                                  se_bih1 + d * 3 * HS,
                                  xw + (long)d * S_LEN * B_SZ * 3 * HS,
                                  S_LEN * B_SZ, 3 * HS, 2 * HS);
    }
    cudaMemsetAsync(hsF[2], 0, sizeof(float) * HSBUF_N);
    cudaMemsetAsync(hsB[2], 0, sizeof(bf) * HSBUF_N);
    cudaMemsetAsync(hsS[2], 0, sizeof(bf) * HSBUF_N);
    cudaMemsetAsync(bar, 0, sizeof(unsigned));
    gru_sent_persistent<<<NBLK_S, 256, SMEM_PERS>>>(
        sH1b, sH1s, se_bhh1, xw,
        hsF[2], hsB[2], hsS[2], hsF[3], hsB[3], hsS[3],
        (bf*)0, bar);

    /* 7. output [1, 128, 2800] = [sf0|sb0|sf1|sb1] per batch row */
    concat4_k<<<((long)B_SZ * 4 * HS + 255) / 256, 256>>>(hsF[0], hsF[2],
                                                          (float*)d_out,
                                                          B_SZ, HS, HS);
}